// round 1
// baseline (speedup 1.0000x reference)
#include <cuda_runtime.h>
#include <cuda_bf16.h>
#include <cstdint>

// Shapes (fixed by the problem)
#define BB 8
#define SS 256
#define HH 512
#define GG 8
#define LL 16
#define HD 64
#define LHD (LL*HD)   // 1024

// Scratch (device globals — no allocation allowed)
__device__ float d_Q[BB*SS*HH];        // [B,S,H]     4 MB
__device__ float d_K[BB*SS*HH];        // [B,S,H]     4 MB
__device__ float d_V[BB*SS*LHD];       // [B,S,L*HD]  8 MB
__device__ float d_G[BB*GG*SS*SS];     // [B,G,S,S]  16.7 MB
__device__ float d_A[BB*LL*SS*SS];     // [B,L,S,S]  33.5 MB
__device__ float d_O[BB*SS*LHD];       // [B,S,L*HD]  8 MB

// ---------------------------------------------------------------------------
// Generic row-major SGEMM: C[M,N] = A[M,K] @ B[K,N] (+ bias[N])
// 64x64 tile, 256 threads, 4x4 per thread, K-tile 16.
// Assumes M%64==0, N%64==0, K%16==0 (true for all our shapes).
// ---------------------------------------------------------------------------
__global__ void gemm_kernel(const float* __restrict__ A, const float* __restrict__ B,
                            const float* __restrict__ bias, float* __restrict__ C,
                            int M, int N, int K) {
    __shared__ float As[16][65];
    __shared__ float Bs[16][65];
    const int tid = threadIdx.x;
    const int tx = tid & 15, ty = tid >> 4;
    const int row0 = blockIdx.y * 64;
    const int col0 = blockIdx.x * 64;
    float acc[4][4] = {};
    for (int k0 = 0; k0 < K; k0 += 16) {
        #pragma unroll
        for (int i = tid; i < 64 * 16; i += 256) {
            int r = i >> 4, c = i & 15;
            As[c][r] = A[(size_t)(row0 + r) * K + k0 + c];
        }
        #pragma unroll
        for (int i = tid; i < 16 * 64; i += 256) {
            int r = i >> 6, c = i & 63;
            Bs[r][c] = B[(size_t)(k0 + r) * N + col0 + c];
        }
        __syncthreads();
        #pragma unroll
        for (int kk = 0; kk < 16; kk++) {
            float a[4], b[4];
            #pragma unroll
            for (int i = 0; i < 4; i++) a[i] = As[kk][ty * 4 + i];
            #pragma unroll
            for (int j = 0; j < 4; j++) b[j] = Bs[kk][tx * 4 + j];
            #pragma unroll
            for (int i = 0; i < 4; i++)
                #pragma unroll
                for (int j = 0; j < 4; j++) acc[i][j] += a[i] * b[j];
        }
        __syncthreads();
    }
    #pragma unroll
    for (int i = 0; i < 4; i++) {
        #pragma unroll
        for (int j = 0; j < 4; j++) {
            int r = row0 + ty * 4 + i, c = col0 + tx * 4 + j;
            float v = acc[i][j];
            if (bias) v += bias[c];
            C[(size_t)r * N + c] = v;
        }
    }
}

// ---------------------------------------------------------------------------
// Scores: G[b,g,s,t] = scale * <Q[b,s,g*64:],K[b,t,g*64:]> + sp[b,s,t] + ed[b,s,t]
// One block per 64x64 (s,t) tile per (b,g). 256 threads.
// ---------------------------------------------------------------------------
__global__ void scores_kernel(const float* __restrict__ sp, const float* __restrict__ ed) {
    const int b = blockIdx.z >> 3, g = blockIdx.z & 7;
    const int s0 = blockIdx.y * 64, t0 = blockIdx.x * 64;
    __shared__ float Qs[64][65];   // [d][s]
    __shared__ float Ks[64][65];   // [d][t]
    const int tid = threadIdx.x;
    #pragma unroll
    for (int i = tid; i < 64 * 64; i += 256) {
        int r = i >> 6, d = i & 63;
        Qs[d][r] = d_Q[((size_t)(b * SS) + s0 + r) * HH + g * 64 + d];
        Ks[d][r] = d_K[((size_t)(b * SS) + t0 + r) * HH + g * 64 + d];
    }
    __syncthreads();
    const int tx = tid & 15, ty = tid >> 4;
    float acc[4][4] = {};
    #pragma unroll 8
    for (int d = 0; d < 64; d++) {
        float a[4], bq[4];
        #pragma unroll
        for (int i = 0; i < 4; i++) a[i] = Qs[d][ty * 4 + i];
        #pragma unroll
        for (int j = 0; j < 4; j++) bq[j] = Ks[d][tx * 4 + j];
        #pragma unroll
        for (int i = 0; i < 4; i++)
            #pragma unroll
            for (int j = 0; j < 4; j++) acc[i][j] += a[i] * bq[j];
    }
    const float scale = 0.04419417382415922f;  // 512^-0.5
    #pragma unroll
    for (int i = 0; i < 4; i++) {
        #pragma unroll
        for (int j = 0; j < 4; j++) {
            int s = s0 + ty * 4 + i, t = t0 + tx * 4 + j;
            size_t bst = ((size_t)b * SS + s) * SS + t;
            d_G[(((size_t)(b * GG + g)) * SS + s) * SS + t] =
                acc[i][j] * scale + sp[bst] + ed[bst];
        }
    }
}

// ---------------------------------------------------------------------------
// Fused relu-sum-over-g + diagonal sigma*eps correction + pad + softmax.
// One block per (b,s); 256 threads = columns t. Reuses the 8 G values (regs)
// across all 16 l heads.
// ---------------------------------------------------------------------------
__global__ void attn_softmax_kernel(const float* __restrict__ p,
                                    const float* __restrict__ sigma,
                                    const float* __restrict__ eps_diag) {
    const int b = blockIdx.x >> 8;
    const int s = blockIdx.x & 255;
    const int t = threadIdx.x;
    float gv[GG];
    #pragma unroll
    for (int g = 0; g < GG; g++)
        gv[g] = d_G[(((size_t)(b * GG + g)) * SS + s) * SS + t];

    __shared__ unsigned padmask;
    __shared__ float sh[16];
    __shared__ float s_p[GG * LL];
    __shared__ float s_sig2[GG];
    __shared__ float s_eps[LL];
    if (t == 0) padmask = 0u;
    if (t < GG * LL) s_p[t] = p[t];
    if (t < GG) { float sg = sigma[t]; s_sig2[t] = sg * sg; }
    if (t < LL) s_eps[t] = eps_diag[t * SS + s];
    __syncthreads();

    unsigned local = 0;
    #pragma unroll
    for (int g = 0; g < GG; g++) if (gv[g] != 0.0f) local |= (1u << g);
    #pragma unroll
    for (int off = 16; off > 0; off >>= 1) local |= __shfl_xor_sync(0xffffffffu, local, off);
    if ((t & 31) == 0) atomicOr(&padmask, local);
    __syncthreads();
    const bool zero_row = (padmask != 0xFFu);

    for (int l = 0; l < LL; l++) {
        float val = 0.f;
        if (!zero_row) {
            #pragma unroll
            for (int g = 0; g < GG; g++) {
                float xg = gv[g];
                if (t == s) xg += s_sig2[g] * s_eps[l];
                val += fmaxf(s_p[g * LL + l] * xg, 0.f);
            }
        }
        // block max
        float m = val;
        #pragma unroll
        for (int off = 16; off > 0; off >>= 1) m = fmaxf(m, __shfl_xor_sync(0xffffffffu, m, off));
        if ((t & 31) == 0) sh[t >> 5] = m;
        __syncthreads();
        if (t < 32) {
            float mm = sh[t & 7];
            #pragma unroll
            for (int off = 4; off > 0; off >>= 1) mm = fmaxf(mm, __shfl_xor_sync(0xffffffffu, mm, off));
            if (t == 0) sh[8] = mm;
        }
        __syncthreads();
        m = sh[8];
        float e = zero_row ? 0.f : __expf(val - m);
        // block sum
        float sum = e;
        #pragma unroll
        for (int off = 16; off > 0; off >>= 1) sum += __shfl_xor_sync(0xffffffffu, sum, off);
        __syncthreads();
        if ((t & 31) == 0) sh[t >> 5] = sum;
        __syncthreads();
        if (t < 32) {
            float ss2 = sh[t & 7];
            #pragma unroll
            for (int off = 4; off > 0; off >>= 1) ss2 += __shfl_xor_sync(0xffffffffu, ss2, off);
            if (t == 0) sh[8] = ss2;
        }
        __syncthreads();
        sum = sh[8];
        d_A[(((size_t)(b * LL + l)) * SS + s) * SS + t] = zero_row ? 0.f : (e / sum);
        __syncthreads();
    }
}

// ---------------------------------------------------------------------------
// O[b,s,l*64+d] = sum_t A[b,l,s,t] * V[b,t,l*64+d]
// One block per (b,l, s-tile of 64). 256 threads, 64x64 output tile, T-tile 32.
// ---------------------------------------------------------------------------
__global__ void av_kernel() {
    const int b = blockIdx.z >> 4, l = blockIdx.z & 15;
    const int s0 = blockIdx.y * 64;
    __shared__ float As[32][65];  // [t][s]
    __shared__ float Vs[32][65];  // [t][d]
    const int tid = threadIdx.x;
    const int tx = tid & 15, ty = tid >> 4;
    float acc[4][4] = {};
    const float* Abase = d_A + (((size_t)(b * LL + l)) * SS) * SS;
    const float* Vbase = d_V + (size_t)b * SS * LHD + l * HD;
    for (int t0 = 0; t0 < SS; t0 += 32) {
        #pragma unroll
        for (int i = tid; i < 64 * 32; i += 256) {
            int r = i >> 5, c = i & 31;
            As[c][r] = Abase[(size_t)(s0 + r) * SS + t0 + c];
        }
        #pragma unroll
        for (int i = tid; i < 32 * 64; i += 256) {
            int r = i >> 6, d = i & 63;
            Vs[r][d] = Vbase[(size_t)(t0 + r) * LHD + d];
        }
        __syncthreads();
        #pragma unroll
        for (int kk = 0; kk < 32; kk++) {
            float a[4], v[4];
            #pragma unroll
            for (int i = 0; i < 4; i++) a[i] = As[kk][ty * 4 + i];
            #pragma unroll
            for (int j = 0; j < 4; j++) v[j] = Vs[kk][tx * 4 + j];
            #pragma unroll
            for (int i = 0; i < 4; i++)
                #pragma unroll
                for (int j = 0; j < 4; j++) acc[i][j] += a[i] * v[j];
        }
        __syncthreads();
    }
    float* Obase = d_O + (size_t)b * SS * LHD + l * HD;
    #pragma unroll
    for (int i = 0; i < 4; i++)
        #pragma unroll
        for (int j = 0; j < 4; j++)
            Obase[(size_t)(s0 + ty * 4 + i) * LHD + tx * 4 + j] = acc[i][j];
}

// ---------------------------------------------------------------------------
extern "C" void kernel_launch(void* const* d_in, const int* in_sizes, int n_in,
                              void* d_out, int out_size) {
    (void)in_sizes; (void)n_in; (void)out_size;
    const float* x    = (const float*)d_in[0];
    const float* sp   = (const float*)d_in[1];
    const float* ed   = (const float*)d_in[2];
    const float* Wq   = (const float*)d_in[3];
    const float* Wk   = (const float*)d_in[4];
    const float* Wv   = (const float*)d_in[5];
    const float* bv   = (const float*)d_in[6];
    const float* sig  = (const float*)d_in[7];
    const float* p    = (const float*)d_in[8];
    const float* eps  = (const float*)d_in[9];
    const float* Wout = (const float*)d_in[10];
    const float* bout = (const float*)d_in[11];
    float* out = (float*)d_out;

    float *Qp, *Kp, *Vp, *Op;
    cudaGetSymbolAddress((void**)&Qp, d_Q);
    cudaGetSymbolAddress((void**)&Kp, d_K);
    cudaGetSymbolAddress((void**)&Vp, d_V);
    cudaGetSymbolAddress((void**)&Op, d_O);

    dim3 blk(256);
    // 1) QKV projections
    gemm_kernel<<<dim3(HH / 64, (BB * SS) / 64), blk>>>(x, Wq, nullptr, Qp, BB * SS, HH, HH);
    gemm_kernel<<<dim3(HH / 64, (BB * SS) / 64), blk>>>(x, Wk, nullptr, Kp, BB * SS, HH, HH);
    gemm_kernel<<<dim3(LHD / 64, (BB * SS) / 64), blk>>>(x, Wv, bv, Vp, BB * SS, LHD, HH);
    // 2) scores + bias
    scores_kernel<<<dim3(SS / 64, SS / 64, BB * GG), blk>>>(sp, ed);
    // 3) relu-sum over g + softmax
    attn_softmax_kernel<<<dim3(BB * SS), blk>>>(p, sig, eps);
    // 4) A @ V
    av_kernel<<<dim3(1, SS / 64, BB * LL), blk>>>();
    // 5) output projection
    gemm_kernel<<<dim3(HH / 64, (BB * SS) / 64), blk>>>(Op, Wout, bout, out, BB * SS, HH, LHD);
}

// round 2
// speedup vs baseline: 2.0360x; 2.0360x over previous
#include <cuda_runtime.h>
#include <cuda_bf16.h>
#include <cstdint>

// Shapes (fixed by the problem)
#define BB 8
#define SS 256
#define HH 512
#define GG 8
#define LL 16
#define HD 64
#define LHD (LL*HD)   // 1024

// Scratch (device globals — no allocation allowed)
__device__ float d_Q[BB*SS*HH];        // [B,S,H]     4 MB
__device__ float d_K[BB*SS*HH];        // [B,S,H]     4 MB
__device__ float d_V[BB*SS*LHD];       // [B,S,L*HD]  8 MB
__device__ float d_G[BB*GG*SS*SS];     // [B,G,S,S]  16.7 MB
__device__ float d_A[BB*LL*SS*SS];     // [B,L,S,S]  33.5 MB
__device__ float d_O[BB*SS*LHD];       // [B,S,L*HD]  8 MB

// ---------------------------------------------------------------------------
// TF32 tensor-core GEMM: C[M,N] = A[M,K] @ B[K,N] (+ bias[N])
// A row-major [M,K], B row-major [K,N], C row-major [M,N].
// Block tile 128x64, K-tile 16, 256 threads (8 warps as 4x2 of 32x32 warp tiles).
// mma.m16n8k8 tf32, fp32 accumulate. Double-buffered smem.
// Requires M%128==0, N%64==0, K%16==0.
// ---------------------------------------------------------------------------
__device__ __forceinline__ unsigned f2tf32(float x) {
    unsigned r;
    asm("cvt.rna.tf32.f32 %0, %1;" : "=r"(r) : "f"(x));
    return r;
}

__device__ __forceinline__ void mma_tf32(float* c, const unsigned* a, const unsigned* b) {
    asm volatile(
        "mma.sync.aligned.m16n8k8.row.col.f32.tf32.tf32.f32 "
        "{%0,%1,%2,%3}, {%4,%5,%6,%7}, {%8,%9}, {%0,%1,%2,%3};"
        : "+f"(c[0]), "+f"(c[1]), "+f"(c[2]), "+f"(c[3])
        : "r"(a[0]), "r"(a[1]), "r"(a[2]), "r"(a[3]), "r"(b[0]), "r"(b[1]));
}

__global__ void gemm_tf32_kernel(const float* __restrict__ A, int lda,
                                 const float* __restrict__ B, int ldb,
                                 const float* __restrict__ bias,
                                 float* __restrict__ C, int ldc,
                                 int M, int N, int K) {
    // As: [k][m] (k-major), pad so k-stride = 136 -> 4*k+m bank spread
    // Bs: [n][k] (n-major), stride 20 -> distinct banks across n
    __shared__ unsigned As[2][16][136];
    __shared__ unsigned Bs[2][64][20];

    const int tid = threadIdx.x;
    const int warp = tid >> 5, lane = tid & 31;
    const int gid = lane >> 2, tig = lane & 3;
    const int wm = warp & 3, wn = warp >> 2;          // 4 x 2 warp grid
    const int row0 = blockIdx.y * 128, col0 = blockIdx.x * 64;

    float c[2][4][4] = {};

    // gmem load indices (fixed per thread)
    const int a_r = tid >> 2;           // 0..63 (and +64)
    const int a_c4 = (tid & 3) * 4;     // k offset within tile
    const int b_k = tid >> 4;           // 0..15
    const int b_n4 = (tid & 15) * 4;    // n offset within tile

    const float* Abase0 = A + (size_t)(row0 + a_r) * lda + a_c4;
    const float* Abase1 = A + (size_t)(row0 + a_r + 64) * lda + a_c4;
    const float* Bbase  = B + (size_t)b_k * ldb + col0 + b_n4;

    const int KT = K / 16;

    // load tile 0
    float4 pa0 = *(const float4*)(Abase0);
    float4 pa1 = *(const float4*)(Abase1);
    float4 pb  = *(const float4*)(Bbase);
    {
        As[0][a_c4 + 0][a_r] = f2tf32(pa0.x); As[0][a_c4 + 1][a_r] = f2tf32(pa0.y);
        As[0][a_c4 + 2][a_r] = f2tf32(pa0.z); As[0][a_c4 + 3][a_r] = f2tf32(pa0.w);
        As[0][a_c4 + 0][a_r + 64] = f2tf32(pa1.x); As[0][a_c4 + 1][a_r + 64] = f2tf32(pa1.y);
        As[0][a_c4 + 2][a_r + 64] = f2tf32(pa1.z); As[0][a_c4 + 3][a_r + 64] = f2tf32(pa1.w);
        Bs[0][b_n4 + 0][b_k] = f2tf32(pb.x); Bs[0][b_n4 + 1][b_k] = f2tf32(pb.y);
        Bs[0][b_n4 + 2][b_k] = f2tf32(pb.z); Bs[0][b_n4 + 3][b_k] = f2tf32(pb.w);
    }
    __syncthreads();

    int buf = 0;
    for (int kt = 0; kt < KT; kt++) {
        const bool has_next = (kt + 1) < KT;
        if (has_next) {
            const int k0 = (kt + 1) * 16;
            pa0 = *(const float4*)(Abase0 + k0);
            pa1 = *(const float4*)(Abase1 + k0);
            pb  = *(const float4*)(Bbase + (size_t)k0 * ldb);
        }

        // compute on buf
        #pragma unroll
        for (int ks = 0; ks < 16; ks += 8) {
            unsigned af[2][4], bf[4][2];
            #pragma unroll
            for (int mt = 0; mt < 2; mt++) {
                const int mb = wm * 32 + mt * 16 + gid;
                af[mt][0] = As[buf][ks + tig][mb];
                af[mt][1] = As[buf][ks + tig][mb + 8];
                af[mt][2] = As[buf][ks + tig + 4][mb];
                af[mt][3] = As[buf][ks + tig + 4][mb + 8];
            }
            #pragma unroll
            for (int nt = 0; nt < 4; nt++) {
                const int nb = wn * 32 + nt * 8 + gid;
                bf[nt][0] = Bs[buf][nb][ks + tig];
                bf[nt][1] = Bs[buf][nb][ks + tig + 4];
            }
            #pragma unroll
            for (int mt = 0; mt < 2; mt++)
                #pragma unroll
                for (int nt = 0; nt < 4; nt++)
                    mma_tf32(c[mt][nt], af[mt], bf[nt]);
        }

        if (has_next) {
            const int nb = buf ^ 1;
            As[nb][a_c4 + 0][a_r] = f2tf32(pa0.x); As[nb][a_c4 + 1][a_r] = f2tf32(pa0.y);
            As[nb][a_c4 + 2][a_r] = f2tf32(pa0.z); As[nb][a_c4 + 3][a_r] = f2tf32(pa0.w);
            As[nb][a_c4 + 0][a_r + 64] = f2tf32(pa1.x); As[nb][a_c4 + 1][a_r + 64] = f2tf32(pa1.y);
            As[nb][a_c4 + 2][a_r + 64] = f2tf32(pa1.z); As[nb][a_c4 + 3][a_r + 64] = f2tf32(pa1.w);
            Bs[nb][b_n4 + 0][b_k] = f2tf32(pb.x); Bs[nb][b_n4 + 1][b_k] = f2tf32(pb.y);
            Bs[nb][b_n4 + 2][b_k] = f2tf32(pb.z); Bs[nb][b_n4 + 3][b_k] = f2tf32(pb.w);
        }
        __syncthreads();
        buf ^= 1;
    }

    // epilogue
    #pragma unroll
    for (int mt = 0; mt < 2; mt++) {
        #pragma unroll
        for (int nt = 0; nt < 4; nt++) {
            const int r = row0 + wm * 32 + mt * 16 + gid;
            const int cc = col0 + wn * 32 + nt * 8 + 2 * tig;
            float b0 = bias ? bias[cc] : 0.f;
            float b1 = bias ? bias[cc + 1] : 0.f;
            C[(size_t)r * ldc + cc]           = c[mt][nt][0] + b0;
            C[(size_t)r * ldc + cc + 1]       = c[mt][nt][1] + b1;
            C[(size_t)(r + 8) * ldc + cc]     = c[mt][nt][2] + b0;
            C[(size_t)(r + 8) * ldc + cc + 1] = c[mt][nt][3] + b1;
        }
    }
}

// ---------------------------------------------------------------------------
// Scores: G[b,g,s,t] = scale * <Q[b,s,g*64:],K[b,t,g*64:]> + sp[b,s,t] + ed[b,s,t]
// ---------------------------------------------------------------------------
__global__ void scores_kernel(const float* __restrict__ sp, const float* __restrict__ ed) {
    const int b = blockIdx.z >> 3, g = blockIdx.z & 7;
    const int s0 = blockIdx.y * 64, t0 = blockIdx.x * 64;
    __shared__ float Qs[64][65];   // [d][s]
    __shared__ float Ks[64][65];   // [d][t]
    const int tid = threadIdx.x;
    #pragma unroll
    for (int i = tid; i < 64 * 64; i += 256) {
        int r = i >> 6, d = i & 63;
        Qs[d][r] = d_Q[((size_t)(b * SS) + s0 + r) * HH + g * 64 + d];
        Ks[d][r] = d_K[((size_t)(b * SS) + t0 + r) * HH + g * 64 + d];
    }
    __syncthreads();
    const int tx = tid & 15, ty = tid >> 4;
    float acc[4][4] = {};
    #pragma unroll 8
    for (int d = 0; d < 64; d++) {
        float a[4], bq[4];
        #pragma unroll
        for (int i = 0; i < 4; i++) a[i] = Qs[d][ty * 4 + i];
        #pragma unroll
        for (int j = 0; j < 4; j++) bq[j] = Ks[d][tx * 4 + j];
        #pragma unroll
        for (int i = 0; i < 4; i++)
            #pragma unroll
            for (int j = 0; j < 4; j++) acc[i][j] += a[i] * bq[j];
    }
    const float scale = 0.04419417382415922f;  // 512^-0.5
    #pragma unroll
    for (int i = 0; i < 4; i++) {
        #pragma unroll
        for (int j = 0; j < 4; j++) {
            int s = s0 + ty * 4 + i, t = t0 + tx * 4 + j;
            size_t bst = ((size_t)b * SS + s) * SS + t;
            d_G[(((size_t)(b * GG + g)) * SS + s) * SS + t] =
                acc[i][j] * scale + sp[bst] + ed[bst];
        }
    }
}

// ---------------------------------------------------------------------------
// Fused relu-sum-over-g + diagonal sigma*eps correction + pad + softmax.
// ---------------------------------------------------------------------------
__global__ void attn_softmax_kernel(const float* __restrict__ p,
                                    const float* __restrict__ sigma,
                                    const float* __restrict__ eps_diag) {
    const int b = blockIdx.x >> 8;
    const int s = blockIdx.x & 255;
    const int t = threadIdx.x;
    float gv[GG];
    #pragma unroll
    for (int g = 0; g < GG; g++)
        gv[g] = d_G[(((size_t)(b * GG + g)) * SS + s) * SS + t];

    __shared__ unsigned padmask;
    __shared__ float sh[16];
    __shared__ float s_p[GG * LL];
    __shared__ float s_sig2[GG];
    __shared__ float s_eps[LL];
    if (t == 0) padmask = 0u;
    if (t < GG * LL) s_p[t] = p[t];
    if (t < GG) { float sg = sigma[t]; s_sig2[t] = sg * sg; }
    if (t < LL) s_eps[t] = eps_diag[t * SS + s];
    __syncthreads();

    unsigned local = 0;
    #pragma unroll
    for (int g = 0; g < GG; g++) if (gv[g] != 0.0f) local |= (1u << g);
    #pragma unroll
    for (int off = 16; off > 0; off >>= 1) local |= __shfl_xor_sync(0xffffffffu, local, off);
    if ((t & 31) == 0) atomicOr(&padmask, local);
    __syncthreads();
    const bool zero_row = (padmask != 0xFFu);

    for (int l = 0; l < LL; l++) {
        float val = 0.f;
        if (!zero_row) {
            #pragma unroll
            for (int g = 0; g < GG; g++) {
                float xg = gv[g];
                if (t == s) xg += s_sig2[g] * s_eps[l];
                val += fmaxf(s_p[g * LL + l] * xg, 0.f);
            }
        }
        // block max
        float m = val;
        #pragma unroll
        for (int off = 16; off > 0; off >>= 1) m = fmaxf(m, __shfl_xor_sync(0xffffffffu, m, off));
        if ((t & 31) == 0) sh[t >> 5] = m;
        __syncthreads();
        if (t < 32) {
            float mm = sh[t & 7];
            #pragma unroll
            for (int off = 4; off > 0; off >>= 1) mm = fmaxf(mm, __shfl_xor_sync(0xffffffffu, mm, off));
            if (t == 0) sh[8] = mm;
        }
        __syncthreads();
        m = sh[8];
        float e = zero_row ? 0.f : __expf(val - m);
        // block sum
        float sum = e;
        #pragma unroll
        for (int off = 16; off > 0; off >>= 1) sum += __shfl_xor_sync(0xffffffffu, sum, off);
        __syncthreads();
        if ((t & 31) == 0) sh[t >> 5] = sum;
        __syncthreads();
        if (t < 32) {
            float ss2 = sh[t & 7];
            #pragma unroll
            for (int off = 4; off > 0; off >>= 1) ss2 += __shfl_xor_sync(0xffffffffu, ss2, off);
            if (t == 0) sh[8] = ss2;
        }
        __syncthreads();
        sum = sh[8];
        d_A[(((size_t)(b * LL + l)) * SS + s) * SS + t] = zero_row ? 0.f : (e / sum);
        __syncthreads();
    }
}

// ---------------------------------------------------------------------------
// O[b,s,l*64+d] = sum_t A[b,l,s,t] * V[b,t,l*64+d]
// ---------------------------------------------------------------------------
__global__ void av_kernel() {
    const int b = blockIdx.z >> 4, l = blockIdx.z & 15;
    const int s0 = blockIdx.y * 64;
    __shared__ float As[32][65];  // [t][s]
    __shared__ float Vs[32][65];  // [t][d]
    const int tid = threadIdx.x;
    const int tx = tid & 15, ty = tid >> 4;
    float acc[4][4] = {};
    const float* Abase = d_A + (((size_t)(b * LL + l)) * SS) * SS;
    const float* Vbase = d_V + (size_t)b * SS * LHD + l * HD;
    for (int t0 = 0; t0 < SS; t0 += 32) {
        #pragma unroll
        for (int i = tid; i < 64 * 32; i += 256) {
            int r = i >> 5, c = i & 31;
            As[c][r] = Abase[(size_t)(s0 + r) * SS + t0 + c];
        }
        #pragma unroll
        for (int i = tid; i < 32 * 64; i += 256) {
            int r = i >> 6, d = i & 63;
            Vs[r][d] = Vbase[(size_t)(t0 + r) * LHD + d];
        }
        __syncthreads();
        #pragma unroll
        for (int kk = 0; kk < 32; kk++) {
            float a[4], v[4];
            #pragma unroll
            for (int i = 0; i < 4; i++) a[i] = As[kk][ty * 4 + i];
            #pragma unroll
            for (int j = 0; j < 4; j++) v[j] = Vs[kk][tx * 4 + j];
            #pragma unroll
            for (int i = 0; i < 4; i++)
                #pragma unroll
                for (int j = 0; j < 4; j++) acc[i][j] += a[i] * v[j];
        }
        __syncthreads();
    }
    float* Obase = d_O + (size_t)b * SS * LHD + l * HD;
    #pragma unroll
    for (int i = 0; i < 4; i++)
        #pragma unroll
        for (int j = 0; j < 4; j++)
            Obase[(size_t)(s0 + ty * 4 + i) * LHD + tx * 4 + j] = acc[i][j];
}

// ---------------------------------------------------------------------------
extern "C" void kernel_launch(void* const* d_in, const int* in_sizes, int n_in,
                              void* d_out, int out_size) {
    (void)in_sizes; (void)n_in; (void)out_size;
    const float* x    = (const float*)d_in[0];
    const float* sp   = (const float*)d_in[1];
    const float* ed   = (const float*)d_in[2];
    const float* Wq   = (const float*)d_in[3];
    const float* Wk   = (const float*)d_in[4];
    const float* Wv   = (const float*)d_in[5];
    const float* bv   = (const float*)d_in[6];
    const float* sig  = (const float*)d_in[7];
    const float* p    = (const float*)d_in[8];
    const float* eps  = (const float*)d_in[9];
    const float* Wout = (const float*)d_in[10];
    const float* bout = (const float*)d_in[11];
    float* out = (float*)d_out;

    float *Qp, *Kp, *Vp, *Op;
    cudaGetSymbolAddress((void**)&Qp, d_Q);
    cudaGetSymbolAddress((void**)&Kp, d_K);
    cudaGetSymbolAddress((void**)&Vp, d_V);
    cudaGetSymbolAddress((void**)&Op, d_O);

    dim3 blk(256);
    const int M = BB * SS;  // 2048
    // 1) QKV projections (tf32 tensor cores)
    gemm_tf32_kernel<<<dim3(HH / 64, M / 128), blk>>>(x, HH, Wq, HH, nullptr, Qp, HH, M, HH, HH);
    gemm_tf32_kernel<<<dim3(HH / 64, M / 128), blk>>>(x, HH, Wk, HH, nullptr, Kp, HH, M, HH, HH);
    gemm_tf32_kernel<<<dim3(LHD / 64, M / 128), blk>>>(x, HH, Wv, LHD, bv, Vp, LHD, M, LHD, HH);
    // 2) scores + bias
    scores_kernel<<<dim3(SS / 64, SS / 64, BB * GG), blk>>>(sp, ed);
    // 3) relu-sum over g + softmax
    attn_softmax_kernel<<<dim3(BB * SS), blk>>>(p, sig, eps);
    // 4) A @ V
    av_kernel<<<dim3(1, SS / 64, BB * LL), blk>>>();
    // 5) output projection (tf32 tensor cores)
    gemm_tf32_kernel<<<dim3(HH / 64, M / 128), blk>>>(Op, LHD, Wout, HH, bout, out, HH, M, HH, LHD);
}

// round 3
// speedup vs baseline: 2.6281x; 1.2908x over previous
#include <cuda_runtime.h>
#include <cuda_bf16.h>
#include <cstdint>

// Shapes (fixed by the problem)
#define BB 8
#define SS 256
#define HH 512
#define GG 8
#define LL 16
#define HD 64
#define LHD (LL*HD)   // 1024

// Scratch (device globals — no allocation allowed)
__device__ float d_Q[BB*SS*HH];        // [B,S,H]     4 MB
__device__ float d_K[BB*SS*HH];        // [B,S,H]     4 MB
__device__ float d_V[BB*SS*LHD];       // [B,S,L*HD]  8 MB
__device__ float d_G[BB*GG*SS*SS];     // [B,G,S,S]  16.7 MB
__device__ float d_A[BB*LL*SS*SS];     // [B,L,S,S]  33.5 MB
__device__ float d_O[BB*SS*LHD];       // [B,S,L*HD]  8 MB

__device__ __forceinline__ unsigned f2tf32(float x) {
    unsigned r;
    asm("cvt.rna.tf32.f32 %0, %1;" : "=r"(r) : "f"(x));
    return r;
}

__device__ __forceinline__ void mma_tf32(float* c, const unsigned* a, const unsigned* b) {
    asm volatile(
        "mma.sync.aligned.m16n8k8.row.col.f32.tf32.tf32.f32 "
        "{%0,%1,%2,%3}, {%4,%5,%6,%7}, {%8,%9}, {%0,%1,%2,%3};"
        : "+f"(c[0]), "+f"(c[1]), "+f"(c[2]), "+f"(c[3])
        : "r"(a[0]), "r"(a[1]), "r"(a[2]), "r"(a[3]), "r"(b[0]), "r"(b[1]));
}

// ---------------------------------------------------------------------------
// TF32 tensor-core GEMM: C[M,N] = A[M,K] @ B[K,N] (+ bias[N])
// Block tile 128x64, K-tile 16, 256 threads (8 warps: 4x2 of 32x32 warp tiles).
// MODE 0: plain (grid.z == 1), bias optional.
// MODE 1: av-batched: z -> (b,l); A += z*S*S; B,C += b*S*LHD + l*HD. No bias.
// ---------------------------------------------------------------------------
template <int MODE>
__global__ void gemm_tf32_kernel(const float* __restrict__ A, int lda,
                                 const float* __restrict__ B, int ldb,
                                 const float* __restrict__ bias,
                                 float* __restrict__ C, int ldc,
                                 int M, int N, int K) {
    if (MODE == 1) {
        const int z = blockIdx.z;
        const int b = z >> 4, l = z & 15;
        A += (size_t)z * SS * SS;
        const size_t off = (size_t)b * SS * LHD + (size_t)l * HD;
        B += off; C += off;
    }
    __shared__ unsigned As[2][16][136];
    __shared__ unsigned Bs[2][64][20];

    const int tid = threadIdx.x;
    const int warp = tid >> 5, lane = tid & 31;
    const int gid = lane >> 2, tig = lane & 3;
    const int wm = warp & 3, wn = warp >> 2;
    const int row0 = blockIdx.y * 128, col0 = blockIdx.x * 64;

    float c[2][4][4] = {};

    const int a_r = tid >> 2;
    const int a_c4 = (tid & 3) * 4;
    const int b_k = tid >> 4;
    const int b_n4 = (tid & 15) * 4;

    const float* Abase0 = A + (size_t)(row0 + a_r) * lda + a_c4;
    const float* Abase1 = A + (size_t)(row0 + a_r + 64) * lda + a_c4;
    const float* Bbase  = B + (size_t)b_k * ldb + col0 + b_n4;

    const int KT = K / 16;

    float4 pa0 = *(const float4*)(Abase0);
    float4 pa1 = *(const float4*)(Abase1);
    float4 pb  = *(const float4*)(Bbase);
    As[0][a_c4 + 0][a_r] = f2tf32(pa0.x); As[0][a_c4 + 1][a_r] = f2tf32(pa0.y);
    As[0][a_c4 + 2][a_r] = f2tf32(pa0.z); As[0][a_c4 + 3][a_r] = f2tf32(pa0.w);
    As[0][a_c4 + 0][a_r + 64] = f2tf32(pa1.x); As[0][a_c4 + 1][a_r + 64] = f2tf32(pa1.y);
    As[0][a_c4 + 2][a_r + 64] = f2tf32(pa1.z); As[0][a_c4 + 3][a_r + 64] = f2tf32(pa1.w);
    Bs[0][b_n4 + 0][b_k] = f2tf32(pb.x); Bs[0][b_n4 + 1][b_k] = f2tf32(pb.y);
    Bs[0][b_n4 + 2][b_k] = f2tf32(pb.z); Bs[0][b_n4 + 3][b_k] = f2tf32(pb.w);
    __syncthreads();

    int buf = 0;
    for (int kt = 0; kt < KT; kt++) {
        const bool has_next = (kt + 1) < KT;
        if (has_next) {
            const int k0 = (kt + 1) * 16;
            pa0 = *(const float4*)(Abase0 + k0);
            pa1 = *(const float4*)(Abase1 + k0);
            pb  = *(const float4*)(Bbase + (size_t)k0 * ldb);
        }
        #pragma unroll
        for (int ks = 0; ks < 16; ks += 8) {
            unsigned af[2][4], bf[4][2];
            #pragma unroll
            for (int mt = 0; mt < 2; mt++) {
                const int mb = wm * 32 + mt * 16 + gid;
                af[mt][0] = As[buf][ks + tig][mb];
                af[mt][1] = As[buf][ks + tig][mb + 8];
                af[mt][2] = As[buf][ks + tig + 4][mb];
                af[mt][3] = As[buf][ks + tig + 4][mb + 8];
            }
            #pragma unroll
            for (int nt = 0; nt < 4; nt++) {
                const int nb = wn * 32 + nt * 8 + gid;
                bf[nt][0] = Bs[buf][nb][ks + tig];
                bf[nt][1] = Bs[buf][nb][ks + tig + 4];
            }
            #pragma unroll
            for (int mt = 0; mt < 2; mt++)
                #pragma unroll
                for (int nt = 0; nt < 4; nt++)
                    mma_tf32(c[mt][nt], af[mt], bf[nt]);
        }
        if (has_next) {
            const int nb = buf ^ 1;
            As[nb][a_c4 + 0][a_r] = f2tf32(pa0.x); As[nb][a_c4 + 1][a_r] = f2tf32(pa0.y);
            As[nb][a_c4 + 2][a_r] = f2tf32(pa0.z); As[nb][a_c4 + 3][a_r] = f2tf32(pa0.w);
            As[nb][a_c4 + 0][a_r + 64] = f2tf32(pa1.x); As[nb][a_c4 + 1][a_r + 64] = f2tf32(pa1.y);
            As[nb][a_c4 + 2][a_r + 64] = f2tf32(pa1.z); As[nb][a_c4 + 3][a_r + 64] = f2tf32(pa1.w);
            Bs[nb][b_n4 + 0][b_k] = f2tf32(pb.x); Bs[nb][b_n4 + 1][b_k] = f2tf32(pb.y);
            Bs[nb][b_n4 + 2][b_k] = f2tf32(pb.z); Bs[nb][b_n4 + 3][b_k] = f2tf32(pb.w);
        }
        __syncthreads();
        buf ^= 1;
    }

    #pragma unroll
    for (int mt = 0; mt < 2; mt++) {
        #pragma unroll
        for (int nt = 0; nt < 4; nt++) {
            const int r = row0 + wm * 32 + mt * 16 + gid;
            const int cc = col0 + wn * 32 + nt * 8 + 2 * tig;
            float b0 = 0.f, b1 = 0.f;
            if (MODE == 0 && bias) { b0 = bias[cc]; b1 = bias[cc + 1]; }
            C[(size_t)r * ldc + cc]           = c[mt][nt][0] + b0;
            C[(size_t)r * ldc + cc + 1]       = c[mt][nt][1] + b1;
            C[(size_t)(r + 8) * ldc + cc]     = c[mt][nt][2] + b0;
            C[(size_t)(r + 8) * ldc + cc + 1] = c[mt][nt][3] + b1;
        }
    }
}

// ---------------------------------------------------------------------------
// Scores (TF32 MMA): G[b,g,s,t] = scale*<Q[b,s,g*64:],K[b,t,g*64:]> + sp + ed
// z = b*8+g; 128(s) x 64(t) tile; K = 64 (4 k-tiles).
// B operand = K^T: Bs[n][k] = K[t][d] (d contiguous -> float4 along k).
// ---------------------------------------------------------------------------
__global__ void scores_tf32_kernel(const float* __restrict__ sp,
                                   const float* __restrict__ ed) {
    const int z = blockIdx.z;
    const int b = z >> 3, g = z & 7;
    const int row0 = blockIdx.y * 128;   // s
    const int col0 = blockIdx.x * 64;    // t

    __shared__ unsigned As[2][16][136];
    __shared__ unsigned Bs[2][64][20];

    const int tid = threadIdx.x;
    const int warp = tid >> 5, lane = tid & 31;
    const int gid = lane >> 2, tig = lane & 3;
    const int wm = warp & 3, wn = warp >> 2;

    float c[2][4][4] = {};

    const int a_r = tid >> 2;
    const int a_c4 = (tid & 3) * 4;
    const int bn = tid >> 2;           // 0..63 (t within tile)
    const int bk4 = (tid & 3) * 4;     // d within k-tile

    const float* Qb = d_Q + ((size_t)(b * SS)) * HH + g * 64;
    const float* Kb = d_K + ((size_t)(b * SS)) * HH + g * 64;
    const float* Abase0 = Qb + (size_t)(row0 + a_r) * HH + a_c4;
    const float* Abase1 = Qb + (size_t)(row0 + a_r + 64) * HH + a_c4;
    const float* Bbase  = Kb + (size_t)(col0 + bn) * HH + bk4;

    float4 pa0 = *(const float4*)(Abase0);
    float4 pa1 = *(const float4*)(Abase1);
    float4 pb  = *(const float4*)(Bbase);
    As[0][a_c4 + 0][a_r] = f2tf32(pa0.x); As[0][a_c4 + 1][a_r] = f2tf32(pa0.y);
    As[0][a_c4 + 2][a_r] = f2tf32(pa0.z); As[0][a_c4 + 3][a_r] = f2tf32(pa0.w);
    As[0][a_c4 + 0][a_r + 64] = f2tf32(pa1.x); As[0][a_c4 + 1][a_r + 64] = f2tf32(pa1.y);
    As[0][a_c4 + 2][a_r + 64] = f2tf32(pa1.z); As[0][a_c4 + 3][a_r + 64] = f2tf32(pa1.w);
    Bs[0][bn][bk4 + 0] = f2tf32(pb.x); Bs[0][bn][bk4 + 1] = f2tf32(pb.y);
    Bs[0][bn][bk4 + 2] = f2tf32(pb.z); Bs[0][bn][bk4 + 3] = f2tf32(pb.w);
    __syncthreads();

    int buf = 0;
    #pragma unroll
    for (int kt = 0; kt < 4; kt++) {
        const bool has_next = (kt + 1) < 4;
        if (has_next) {
            const int k0 = (kt + 1) * 16;
            pa0 = *(const float4*)(Abase0 + k0);
            pa1 = *(const float4*)(Abase1 + k0);
            pb  = *(const float4*)(Bbase + k0);
        }
        #pragma unroll
        for (int ks = 0; ks < 16; ks += 8) {
            unsigned af[2][4], bf[4][2];
            #pragma unroll
            for (int mt = 0; mt < 2; mt++) {
                const int mb = wm * 32 + mt * 16 + gid;
                af[mt][0] = As[buf][ks + tig][mb];
                af[mt][1] = As[buf][ks + tig][mb + 8];
                af[mt][2] = As[buf][ks + tig + 4][mb];
                af[mt][3] = As[buf][ks + tig + 4][mb + 8];
            }
            #pragma unroll
            for (int nt = 0; nt < 4; nt++) {
                const int nb = wn * 32 + nt * 8 + gid;
                bf[nt][0] = Bs[buf][nb][ks + tig];
                bf[nt][1] = Bs[buf][nb][ks + tig + 4];
            }
            #pragma unroll
            for (int mt = 0; mt < 2; mt++)
                #pragma unroll
                for (int nt = 0; nt < 4; nt++)
                    mma_tf32(c[mt][nt], af[mt], bf[nt]);
        }
        if (has_next) {
            const int nb2 = buf ^ 1;
            As[nb2][a_c4 + 0][a_r] = f2tf32(pa0.x); As[nb2][a_c4 + 1][a_r] = f2tf32(pa0.y);
            As[nb2][a_c4 + 2][a_r] = f2tf32(pa0.z); As[nb2][a_c4 + 3][a_r] = f2tf32(pa0.w);
            As[nb2][a_c4 + 0][a_r + 64] = f2tf32(pa1.x); As[nb2][a_c4 + 1][a_r + 64] = f2tf32(pa1.y);
            As[nb2][a_c4 + 2][a_r + 64] = f2tf32(pa1.z); As[nb2][a_c4 + 3][a_r + 64] = f2tf32(pa1.w);
            Bs[nb2][bn][bk4 + 0] = f2tf32(pb.x); Bs[nb2][bn][bk4 + 1] = f2tf32(pb.y);
            Bs[nb2][bn][bk4 + 2] = f2tf32(pb.z); Bs[nb2][bn][bk4 + 3] = f2tf32(pb.w);
        }
        __syncthreads();
        buf ^= 1;
    }

    const float scale = 0.04419417382415922f;  // 512^-0.5
    float* Gb = d_G + ((size_t)z) * SS * SS;
    const float* spb = sp + ((size_t)b) * SS * SS;
    const float* edb = ed + ((size_t)b) * SS * SS;
    #pragma unroll
    for (int mt = 0; mt < 2; mt++) {
        #pragma unroll
        for (int nt = 0; nt < 4; nt++) {
            const int s = row0 + wm * 32 + mt * 16 + gid;
            const int t = col0 + wn * 32 + nt * 8 + 2 * tig;
            size_t i0 = (size_t)s * SS + t;
            size_t i1 = (size_t)(s + 8) * SS + t;
            Gb[i0]     = c[mt][nt][0] * scale + spb[i0] + edb[i0];
            Gb[i0 + 1] = c[mt][nt][1] * scale + spb[i0 + 1] + edb[i0 + 1];
            Gb[i1]     = c[mt][nt][2] * scale + spb[i1] + edb[i1];
            Gb[i1 + 1] = c[mt][nt][3] * scale + spb[i1 + 1] + edb[i1 + 1];
        }
    }
}

// ---------------------------------------------------------------------------
// Fused relu-sum-over-g + diag correction + pad + softmax.
// Block per (b,s). G row staged in smem once; each warp owns 2 l-heads with
// the t-row distributed 8 values/lane -> all reductions are warp shuffles.
// ---------------------------------------------------------------------------
__global__ void attn_softmax_kernel(const float* __restrict__ p,
                                    const float* __restrict__ sigma,
                                    const float* __restrict__ eps_diag) {
    const int b = blockIdx.x >> 8;
    const int s = blockIdx.x & 255;
    const int tid = threadIdx.x;
    const int warp = tid >> 5, lane = tid & 31;

    __shared__ float gs[GG][SS];       // 8 KB
    __shared__ float s_p[GG * LL];
    __shared__ float s_sig2[GG];
    __shared__ float s_eps[LL];
    __shared__ int s_nz[GG];

    #pragma unroll
    for (int i = tid; i < GG * SS; i += 256) {
        int g = i >> 8, t = i & 255;
        gs[g][t] = d_G[(((size_t)(b * GG + g)) * SS + s) * SS + t];
    }
    if (tid < GG * LL) s_p[tid] = p[tid];
    if (tid < GG) { float sg = sigma[tid]; s_sig2[tid] = sg * sg; }
    if (tid < LL) s_eps[tid] = eps_diag[tid * SS + s];
    __syncthreads();

    // pad check: warp w scans g=w
    {
        bool nzl = false;
        #pragma unroll
        for (int tt = 0; tt < 8; tt++) nzl |= (gs[warp][lane + tt * 32] != 0.0f);
        unsigned bal = __ballot_sync(0xffffffffu, nzl);
        if (lane == 0) s_nz[warp] = (bal != 0u);
    }
    __syncthreads();
    bool zero_row = false;
    #pragma unroll
    for (int g = 0; g < GG; g++) zero_row |= (s_nz[g] == 0);

    #pragma unroll
    for (int i = 0; i < 2; i++) {
        const int l = warp * 2 + i;
        float vals[8];
        float diag[GG];
        #pragma unroll
        for (int g = 0; g < GG; g++) diag[g] = s_sig2[g] * s_eps[l];
        #pragma unroll
        for (int tt = 0; tt < 8; tt++) {
            const int t = lane + tt * 32;
            float v = 0.f;
            #pragma unroll
            for (int g = 0; g < GG; g++) {
                float xg = gs[g][t];
                if (t == s) xg += diag[g];
                v += fmaxf(s_p[g * LL + l] * xg, 0.f);
            }
            vals[tt] = v;
        }
        // warp-wide max
        float m = vals[0];
        #pragma unroll
        for (int tt = 1; tt < 8; tt++) m = fmaxf(m, vals[tt]);
        #pragma unroll
        for (int off = 16; off > 0; off >>= 1) m = fmaxf(m, __shfl_xor_sync(0xffffffffu, m, off));
        // exp + sum
        float e[8], sum = 0.f;
        #pragma unroll
        for (int tt = 0; tt < 8; tt++) { e[tt] = __expf(vals[tt] - m); sum += e[tt]; }
        #pragma unroll
        for (int off = 16; off > 0; off >>= 1) sum += __shfl_xor_sync(0xffffffffu, sum, off);
        const float inv = zero_row ? 0.f : (1.0f / sum);
        float* Arow = d_A + (((size_t)(b * LL + l)) * SS + s) * SS;
        #pragma unroll
        for (int tt = 0; tt < 8; tt++) Arow[lane + tt * 32] = e[tt] * inv;
    }
}

// ---------------------------------------------------------------------------
extern "C" void kernel_launch(void* const* d_in, const int* in_sizes, int n_in,
                              void* d_out, int out_size) {
    (void)in_sizes; (void)n_in; (void)out_size;
    const float* x    = (const float*)d_in[0];
    const float* sp   = (const float*)d_in[1];
    const float* ed   = (const float*)d_in[2];
    const float* Wq   = (const float*)d_in[3];
    const float* Wk   = (const float*)d_in[4];
    const float* Wv   = (const float*)d_in[5];
    const float* bv   = (const float*)d_in[6];
    const float* sig  = (const float*)d_in[7];
    const float* p    = (const float*)d_in[8];
    const float* eps  = (const float*)d_in[9];
    const float* Wout = (const float*)d_in[10];
    const float* bout = (const float*)d_in[11];
    float* out = (float*)d_out;

    float *Qp, *Kp, *Vp, *Ap, *Op;
    cudaGetSymbolAddress((void**)&Qp, d_Q);
    cudaGetSymbolAddress((void**)&Kp, d_K);
    cudaGetSymbolAddress((void**)&Vp, d_V);
    cudaGetSymbolAddress((void**)&Ap, d_A);
    cudaGetSymbolAddress((void**)&Op, d_O);

    dim3 blk(256);
    const int M = BB * SS;  // 2048
    // 1) QKV projections
    gemm_tf32_kernel<0><<<dim3(HH / 64, M / 128), blk>>>(x, HH, Wq, HH, nullptr, Qp, HH, M, HH, HH);
    gemm_tf32_kernel<0><<<dim3(HH / 64, M / 128), blk>>>(x, HH, Wk, HH, nullptr, Kp, HH, M, HH, HH);
    gemm_tf32_kernel<0><<<dim3(LHD / 64, M / 128), blk>>>(x, HH, Wv, LHD, bv, Vp, LHD, M, LHD, HH);
    // 2) scores + bias (tensor cores)
    scores_tf32_kernel<<<dim3(SS / 64, SS / 128, BB * GG), blk>>>(sp, ed);
    // 3) relu-sum over g + softmax (warp-per-l)
    attn_softmax_kernel<<<dim3(BB * SS), blk>>>(p, sig, eps);
    // 4) A @ V (tensor cores, batched over (b,l))
    gemm_tf32_kernel<1><<<dim3(1, SS / 128, BB * LL), blk>>>(Ap, SS, Vp, LHD, nullptr, Op, LHD, SS, HD, SS);
    // 5) output projection
    gemm_tf32_kernel<0><<<dim3(HH / 64, M / 128), blk>>>(Op, LHD, Wout, HH, bout, out, HH, M, HH, LHD);
}

// round 5
// speedup vs baseline: 3.4489x; 1.3123x over previous
#include <cuda_runtime.h>
#include <cuda_bf16.h>
#include <cstdint>

// Shapes (fixed by the problem)
#define BB 8
#define SS 256
#define HH 512
#define GG 8
#define LL 16
#define HD 64
#define LHD (LL*HD)   // 1024

// Scratch (device globals — no allocation allowed)
__device__ float d_Q[BB*SS*HH];
__device__ float d_K[BB*SS*HH];
__device__ float d_V[BB*SS*LHD];
__device__ float d_G[BB*GG*SS*SS];
__device__ float d_A[BB*LL*SS*SS];
__device__ float d_O[BB*SS*LHD];

__device__ __forceinline__ unsigned f2tf32(float x) {
    unsigned r;
    asm("cvt.rna.tf32.f32 %0, %1;" : "=r"(r) : "f"(x));
    return r;
}

__device__ __forceinline__ void mma_tf32(float* c, const unsigned* a, const unsigned* b) {
    asm volatile(
        "mma.sync.aligned.m16n8k8.row.col.f32.tf32.tf32.f32 "
        "{%0,%1,%2,%3}, {%4,%5,%6,%7}, {%8,%9}, {%0,%1,%2,%3};"
        : "+f"(c[0]), "+f"(c[1]), "+f"(c[2]), "+f"(c[3])
        : "r"(a[0]), "r"(a[1]), "r"(a[2]), "r"(a[3]), "r"(b[0]), "r"(b[1]));
}

__device__ __forceinline__ void cp16(unsigned dst, const void* src) {
    asm volatile("cp.async.ca.shared.global [%0], [%1], 16;" :: "r"(dst), "l"(src));
}
__device__ __forceinline__ void cp_commit() {
    asm volatile("cp.async.commit_group;");
}
template <int N>
__device__ __forceinline__ void cp_wait() {
    asm volatile("cp.async.wait_group %0;" :: "n"(N));
}

// ---------------------------------------------------------------------------
// TF32 GEMM with cp.async 3-stage pipeline. C[M,N] = A[M,K] @ B[K,N] (+bias)
// Block tile 128x64, K-tile 16, 256 threads (8 warps: 4x2 of 32x32 warp tiles).
// MODE 0: plain. MODE 1: av-batched (z->(b,l)). MODE 2: dual-output (Q|K).
// ---------------------------------------------------------------------------
template <int MODE>
__global__ void __launch_bounds__(256)
gemm_tf32_kernel(const float* __restrict__ A, int lda,
                 const float* __restrict__ B, int ldb,
                 const float* __restrict__ bias,
                 float* __restrict__ C, int ldc,
                 int K,
                 const float* __restrict__ B2,
                 float* __restrict__ C2) {
    int col0 = blockIdx.x * 64;
    if (MODE == 1) {
        const int z = blockIdx.z;
        const int b = z >> 4, l = z & 15;
        A += (size_t)z * SS * SS;
        const size_t off = (size_t)b * SS * LHD + (size_t)l * HD;
        B += off; C += off;
    }
    if (MODE == 2) {
        if (col0 >= HH) { B = B2; C = C2; col0 -= HH; }
    }
    const int row0 = blockIdx.y * 128;

    __shared__ float As[3][128][20];   // [m][k], stride 20 (80B, 16B-aligned)
    __shared__ float Bs[3][16][72];    // [k][n], stride 72 (288B, 16B-aligned)

    const int tid = threadIdx.x;
    const int warp = tid >> 5, lane = tid & 31;
    const int gid = lane >> 2, tig = lane & 3;
    const int wm = warp & 3, wn = warp >> 2;

    float c[2][4][4] = {};

    const int a_r = tid >> 2;           // 0..63
    const int a_c4 = (tid & 3) * 4;     // k chunk
    const int b_k = tid >> 4;           // 0..15
    const int b_n4 = (tid & 15) * 4;    // n chunk

    const float* Ag0 = A + (size_t)(row0 + a_r) * lda + a_c4;
    const float* Ag1 = A + (size_t)(row0 + a_r + 64) * lda + a_c4;
    const float* Bg  = B + (size_t)b_k * ldb + col0 + b_n4;

    unsigned dA0[3], dA1[3], dB[3];
    #pragma unroll
    for (int s = 0; s < 3; s++) {
        dA0[s] = (unsigned)__cvta_generic_to_shared(&As[s][a_r][a_c4]);
        dA1[s] = (unsigned)__cvta_generic_to_shared(&As[s][a_r + 64][a_c4]);
        dB[s]  = (unsigned)__cvta_generic_to_shared(&Bs[s][b_k][b_n4]);
    }

    const int KT = K / 16;
    #pragma unroll
    for (int pf = 0; pf < 2; pf++) {
        cp16(dA0[pf], Ag0 + pf * 16);
        cp16(dA1[pf], Ag1 + pf * 16);
        cp16(dB[pf],  Bg + (size_t)(pf * 16) * ldb);
        cp_commit();
    }

    for (int kt = 0; kt < KT; kt++) {
        cp_wait<1>();
        __syncthreads();
        const int st = kt % 3;
        #pragma unroll
        for (int ks = 0; ks < 16; ks += 8) {
            unsigned af[2][4], bf[4][2];
            #pragma unroll
            for (int mt = 0; mt < 2; mt++) {
                const int mb = wm * 32 + mt * 16 + gid;
                af[mt][0] = f2tf32(As[st][mb][ks + tig]);
                af[mt][1] = f2tf32(As[st][mb + 8][ks + tig]);
                af[mt][2] = f2tf32(As[st][mb][ks + tig + 4]);
                af[mt][3] = f2tf32(As[st][mb + 8][ks + tig + 4]);
            }
            #pragma unroll
            for (int nt = 0; nt < 4; nt++) {
                const int nb = wn * 32 + nt * 8 + gid;
                bf[nt][0] = f2tf32(Bs[st][ks + tig][nb]);
                bf[nt][1] = f2tf32(Bs[st][ks + tig + 4][nb]);
            }
            #pragma unroll
            for (int mt = 0; mt < 2; mt++)
                #pragma unroll
                for (int nt = 0; nt < 4; nt++)
                    mma_tf32(c[mt][nt], af[mt], bf[nt]);
        }
        const int ktn = kt + 2;
        if (ktn < KT) {
            const int sn = ktn % 3;
            cp16(dA0[sn], Ag0 + ktn * 16);
            cp16(dA1[sn], Ag1 + ktn * 16);
            cp16(dB[sn],  Bg + (size_t)(ktn * 16) * ldb);
        }
        cp_commit();
    }

    #pragma unroll
    for (int mt = 0; mt < 2; mt++) {
        #pragma unroll
        for (int nt = 0; nt < 4; nt++) {
            const int r = row0 + wm * 32 + mt * 16 + gid;
            const int cc = col0 + wn * 32 + nt * 8 + 2 * tig;
            float b0 = 0.f, b1 = 0.f;
            if (MODE == 0 && bias) { b0 = bias[cc]; b1 = bias[cc + 1]; }
            C[(size_t)r * ldc + cc]           = c[mt][nt][0] + b0;
            C[(size_t)r * ldc + cc + 1]       = c[mt][nt][1] + b1;
            C[(size_t)(r + 8) * ldc + cc]     = c[mt][nt][2] + b0;
            C[(size_t)(r + 8) * ldc + cc + 1] = c[mt][nt][3] + b1;
        }
    }
}

// ---------------------------------------------------------------------------
// Scores (TF32 MMA + cp.async): G = scale*Q·K^T + sp + ed, per (b,g).
// 128(s) x 64(t) tile, K = 64 (4 k-tiles). B operand stored [t][d].
// ---------------------------------------------------------------------------
__global__ void __launch_bounds__(256)
scores_tf32_kernel(const float* __restrict__ sp, const float* __restrict__ ed) {
    const int z = blockIdx.z;
    const int b = z >> 3, g = z & 7;
    const int row0 = blockIdx.y * 128;   // s
    const int col0 = blockIdx.x * 64;    // t

    __shared__ float As[3][128][20];     // Q [s][d]
    __shared__ float Bs[3][64][20];      // K [t][d]

    const int tid = threadIdx.x;
    const int warp = tid >> 5, lane = tid & 31;
    const int gid = lane >> 2, tig = lane & 3;
    const int wm = warp & 3, wn = warp >> 2;

    float c[2][4][4] = {};

    const int a_r = tid >> 2;
    const int a_c4 = (tid & 3) * 4;
    const int bn = tid >> 2;             // t within tile
    const int bk4 = (tid & 3) * 4;       // d chunk

    const float* Qb = d_Q + ((size_t)(b * SS)) * HH + g * 64;
    const float* Kb = d_K + ((size_t)(b * SS)) * HH + g * 64;
    const float* Ag0 = Qb + (size_t)(row0 + a_r) * HH + a_c4;
    const float* Ag1 = Qb + (size_t)(row0 + a_r + 64) * HH + a_c4;
    const float* Bg  = Kb + (size_t)(col0 + bn) * HH + bk4;

    unsigned dA0[3], dA1[3], dB[3];
    #pragma unroll
    for (int s = 0; s < 3; s++) {
        dA0[s] = (unsigned)__cvta_generic_to_shared(&As[s][a_r][a_c4]);
        dA1[s] = (unsigned)__cvta_generic_to_shared(&As[s][a_r + 64][a_c4]);
        dB[s]  = (unsigned)__cvta_generic_to_shared(&Bs[s][bn][bk4]);
    }

    #pragma unroll
    for (int pf = 0; pf < 2; pf++) {
        cp16(dA0[pf], Ag0 + pf * 16);
        cp16(dA1[pf], Ag1 + pf * 16);
        cp16(dB[pf],  Bg + pf * 16);
        cp_commit();
    }

    #pragma unroll
    for (int kt = 0; kt < 4; kt++) {
        cp_wait<1>();
        __syncthreads();
        const int st = kt % 3;
        #pragma unroll
        for (int ks = 0; ks < 16; ks += 8) {
            unsigned af[2][4], bf[4][2];
            #pragma unroll
            for (int mt = 0; mt < 2; mt++) {
                const int mb = wm * 32 + mt * 16 + gid;
                af[mt][0] = f2tf32(As[st][mb][ks + tig]);
                af[mt][1] = f2tf32(As[st][mb + 8][ks + tig]);
                af[mt][2] = f2tf32(As[st][mb][ks + tig + 4]);
                af[mt][3] = f2tf32(As[st][mb + 8][ks + tig + 4]);
            }
            #pragma unroll
            for (int nt = 0; nt < 4; nt++) {
                const int nb = wn * 32 + nt * 8 + gid;
                bf[nt][0] = f2tf32(Bs[st][nb][ks + tig]);
                bf[nt][1] = f2tf32(Bs[st][nb][ks + tig + 4]);
            }
            #pragma unroll
            for (int mt = 0; mt < 2; mt++)
                #pragma unroll
                for (int nt = 0; nt < 4; nt++)
                    mma_tf32(c[mt][nt], af[mt], bf[nt]);
        }
        const int ktn = kt + 2;
        if (ktn < 4) {
            const int sn = ktn % 3;
            cp16(dA0[sn], Ag0 + ktn * 16);
            cp16(dA1[sn], Ag1 + ktn * 16);
            cp16(dB[sn],  Bg + ktn * 16);
        }
        cp_commit();
    }

    const float scale = 0.04419417382415922f;  // 512^-0.5
    float* Gb = d_G + ((size_t)z) * SS * SS;
    const float* spb = sp + ((size_t)b) * SS * SS;
    const float* edb = ed + ((size_t)b) * SS * SS;
    #pragma unroll
    for (int mt = 0; mt < 2; mt++) {
        #pragma unroll
        for (int nt = 0; nt < 4; nt++) {
            const int s = row0 + wm * 32 + mt * 16 + gid;
            const int t = col0 + wn * 32 + nt * 8 + 2 * tig;
            size_t i0 = (size_t)s * SS + t;
            size_t i1 = (size_t)(s + 8) * SS + t;
            Gb[i0]     = c[mt][nt][0] * scale + spb[i0] + edb[i0];
            Gb[i0 + 1] = c[mt][nt][1] * scale + spb[i0 + 1] + edb[i0 + 1];
            Gb[i1]     = c[mt][nt][2] * scale + spb[i1] + edb[i1];
            Gb[i1 + 1] = c[mt][nt][3] * scale + spb[i1 + 1] + edb[i1 + 1];
        }
    }
}

// ---------------------------------------------------------------------------
// Fused relu-sum-over-g + diag correction + pad + softmax (warp-per-2l).
// ---------------------------------------------------------------------------
__global__ void attn_softmax_kernel(const float* __restrict__ p,
                                    const float* __restrict__ sigma,
                                    const float* __restrict__ eps_diag) {
    const int b = blockIdx.x >> 8;
    const int s = blockIdx.x & 255;
    const int tid = threadIdx.x;
    const int warp = tid >> 5, lane = tid & 31;

    __shared__ float gs[GG][SS];
    __shared__ float s_p[GG * LL];
    __shared__ float s_sig2[GG];
    __shared__ float s_eps[LL];
    __shared__ int s_nz[GG];

    #pragma unroll
    for (int i = tid; i < GG * SS; i += 256) {
        int g = i >> 8, t = i & 255;
        gs[g][t] = d_G[(((size_t)(b * GG + g)) * SS + s) * SS + t];
    }
    if (tid < GG * LL) s_p[tid] = p[tid];
    if (tid < GG) { float sg = sigma[tid]; s_sig2[tid] = sg * sg; }
    if (tid < LL) s_eps[tid] = eps_diag[tid * SS + s];
    __syncthreads();

    {
        bool nzl = false;
        #pragma unroll
        for (int tt = 0; tt < 8; tt++) nzl |= (gs[warp][lane + tt * 32] != 0.0f);
        unsigned bal = __ballot_sync(0xffffffffu, nzl);
        if (lane == 0) s_nz[warp] = (bal != 0u);
    }
    __syncthreads();
    bool zero_row = false;
    #pragma unroll
    for (int g = 0; g < GG; g++) zero_row |= (s_nz[g] == 0);

    #pragma unroll
    for (int i = 0; i < 2; i++) {
        const int l = warp * 2 + i;
        float vals[8];
        float diag[GG];
        #pragma unroll
        for (int g = 0; g < GG; g++) diag[g] = s_sig2[g] * s_eps[l];
        #pragma unroll
        for (int tt = 0; tt < 8; tt++) {
            const int t = lane + tt * 32;
            float v = 0.f;
            #pragma unroll
            for (int g = 0; g < GG; g++) {
                float xg = gs[g][t];
                if (t == s) xg += diag[g];
                v += fmaxf(s_p[g * LL + l] * xg, 0.f);
            }
            vals[tt] = v;
        }
        float m = vals[0];
        #pragma unroll
        for (int tt = 1; tt < 8; tt++) m = fmaxf(m, vals[tt]);
        #pragma unroll
        for (int off = 16; off > 0; off >>= 1) m = fmaxf(m, __shfl_xor_sync(0xffffffffu, m, off));
        float e[8], sum = 0.f;
        #pragma unroll
        for (int tt = 0; tt < 8; tt++) { e[tt] = __expf(vals[tt] - m); sum += e[tt]; }
        #pragma unroll
        for (int off = 16; off > 0; off >>= 1) sum += __shfl_xor_sync(0xffffffffu, sum, off);
        const float inv = zero_row ? 0.f : (1.0f / sum);
        float* Arow = d_A + (((size_t)(b * LL + l)) * SS + s) * SS;
        #pragma unroll
        for (int tt = 0; tt < 8; tt++) Arow[lane + tt * 32] = e[tt] * inv;
    }
}

// ---------------------------------------------------------------------------
extern "C" void kernel_launch(void* const* d_in, const int* in_sizes, int n_in,
                              void* d_out, int out_size) {
    (void)in_sizes; (void)n_in; (void)out_size;
    const float* x    = (const float*)d_in[0];
    const float* sp   = (const float*)d_in[1];
    const float* ed   = (const float*)d_in[2];
    const float* Wq   = (const float*)d_in[3];
    const float* Wk   = (const float*)d_in[4];
    const float* Wv   = (const float*)d_in[5];
    const float* bv   = (const float*)d_in[6];
    const float* sig  = (const float*)d_in[7];
    const float* p    = (const float*)d_in[8];
    const float* eps  = (const float*)d_in[9];
    const float* Wout = (const float*)d_in[10];
    const float* bout = (const float*)d_in[11];
    float* out = (float*)d_out;

    float *Qp, *Kp, *Vp, *Ap, *Op;
    cudaGetSymbolAddress((void**)&Qp, d_Q);
    cudaGetSymbolAddress((void**)&Kp, d_K);
    cudaGetSymbolAddress((void**)&Vp, d_V);
    cudaGetSymbolAddress((void**)&Ap, d_A);
    cudaGetSymbolAddress((void**)&Op, d_O);

    dim3 blk(256);
    const int M = BB * SS;  // 2048
    // 1) Q+K fused projection (dual-output), V projection
    gemm_tf32_kernel<2><<<dim3(2 * HH / 64, M / 128), blk>>>(
        x, HH, Wq, HH, nullptr, Qp, HH, HH, Wk, Kp);
    gemm_tf32_kernel<0><<<dim3(LHD / 64, M / 128), blk>>>(
        x, HH, Wv, LHD, bv, Vp, LHD, HH, nullptr, nullptr);
    // 2) scores + bias
    scores_tf32_kernel<<<dim3(SS / 64, SS / 128, BB * GG), blk>>>(sp, ed);
    // 3) relu-sum over g + softmax
    attn_softmax_kernel<<<dim3(BB * SS), blk>>>(p, sig, eps);
    // 4) A @ V (batched over (b,l))
    gemm_tf32_kernel<1><<<dim3(1, SS / 128, BB * LL), blk>>>(
        Ap, SS, Vp, LHD, nullptr, Op, LHD, SS, nullptr, nullptr);
    // 5) output projection
    gemm_tf32_kernel<0><<<dim3(HH / 64, M / 128), blk>>>(
        Op, LHD, Wout, HH, bout, out, HH, LHD, nullptr, nullptr);
}

// round 6
// speedup vs baseline: 3.6616x; 1.0617x over previous
#include <cuda_runtime.h>
#include <cuda_bf16.h>
#include <cstdint>

// Shapes (fixed by the problem)
#define BB 8
#define SS 256
#define HH 512
#define GG 8
#define LL 16
#define HD 64
#define LHD (LL*HD)   // 1024

// Scratch (device globals — no allocation allowed)
__device__ float d_Q[BB*SS*HH];
__device__ float d_K[BB*SS*HH];
__device__ float d_V[BB*SS*LHD];
__device__ float d_G[BB*GG*SS*SS];
__device__ float d_A[BB*LL*SS*SS];
__device__ float d_O[BB*SS*LHD];

__device__ __forceinline__ unsigned f2tf32(float x) {
    unsigned r;
    asm("cvt.rna.tf32.f32 %0, %1;" : "=r"(r) : "f"(x));
    return r;
}

__device__ __forceinline__ void mma_tf32(float* c, const unsigned* a, const unsigned* b) {
    asm volatile(
        "mma.sync.aligned.m16n8k8.row.col.f32.tf32.tf32.f32 "
        "{%0,%1,%2,%3}, {%4,%5,%6,%7}, {%8,%9}, {%0,%1,%2,%3};"
        : "+f"(c[0]), "+f"(c[1]), "+f"(c[2]), "+f"(c[3])
        : "r"(a[0]), "r"(a[1]), "r"(a[2]), "r"(a[3]), "r"(b[0]), "r"(b[1]));
}

__device__ __forceinline__ void cp16(unsigned dst, const void* src) {
    asm volatile("cp.async.ca.shared.global [%0], [%1], 16;" :: "r"(dst), "l"(src));
}
__device__ __forceinline__ void cp_commit() {
    asm volatile("cp.async.commit_group;");
}
template <int N>
__device__ __forceinline__ void cp_wait() {
    asm volatile("cp.async.wait_group %0;" :: "n"(N));
}

// ---------------------------------------------------------------------------
// TF32 GEMM with cp.async 3-stage pipeline. C[M,N] = A[M,K] @ B[K,N] (+bias)
// Block tile 128x64, K-tile 16, 256 threads (8 warps: 4x2 of 32x32 warp tiles).
// MODE 0: plain. MODE 1: av-batched (z->(b,l)). MODE 2: dual-output (Q|K).
// ---------------------------------------------------------------------------
template <int MODE>
__global__ void __launch_bounds__(256)
gemm_tf32_kernel(const float* __restrict__ A, int lda,
                 const float* __restrict__ B, int ldb,
                 const float* __restrict__ bias,
                 float* __restrict__ C, int ldc,
                 int K,
                 const float* __restrict__ B2,
                 float* __restrict__ C2) {
    int col0 = blockIdx.x * 64;
    if (MODE == 1) {
        const int z = blockIdx.z;
        const int b = z >> 4, l = z & 15;
        A += (size_t)z * SS * SS;
        const size_t off = (size_t)b * SS * LHD + (size_t)l * HD;
        B += off; C += off;
    }
    if (MODE == 2) {
        if (col0 >= HH) { B = B2; C = C2; col0 -= HH; }
    }
    const int row0 = blockIdx.y * 128;

    __shared__ float As[3][128][20];   // [m][k]
    __shared__ float Bs[3][16][72];    // [k][n]

    const int tid = threadIdx.x;
    const int warp = tid >> 5, lane = tid & 31;
    const int gid = lane >> 2, tig = lane & 3;
    const int wm = warp & 3, wn = warp >> 2;

    float c[2][4][4] = {};

    const int a_r = tid >> 2;
    const int a_c4 = (tid & 3) * 4;
    const int b_k = tid >> 4;
    const int b_n4 = (tid & 15) * 4;

    const float* Ag0 = A + (size_t)(row0 + a_r) * lda + a_c4;
    const float* Ag1 = A + (size_t)(row0 + a_r + 64) * lda + a_c4;
    const float* Bg  = B + (size_t)b_k * ldb + col0 + b_n4;

    unsigned dA0[3], dA1[3], dB[3];
    #pragma unroll
    for (int s = 0; s < 3; s++) {
        dA0[s] = (unsigned)__cvta_generic_to_shared(&As[s][a_r][a_c4]);
        dA1[s] = (unsigned)__cvta_generic_to_shared(&As[s][a_r + 64][a_c4]);
        dB[s]  = (unsigned)__cvta_generic_to_shared(&Bs[s][b_k][b_n4]);
    }

    const int KT = K / 16;
    #pragma unroll
    for (int pf = 0; pf < 2; pf++) {
        cp16(dA0[pf], Ag0 + pf * 16);
        cp16(dA1[pf], Ag1 + pf * 16);
        cp16(dB[pf],  Bg + (size_t)(pf * 16) * ldb);
        cp_commit();
    }

    for (int kt = 0; kt < KT; kt++) {
        cp_wait<1>();
        __syncthreads();
        const int st = kt % 3;
        #pragma unroll
        for (int ks = 0; ks < 16; ks += 8) {
            unsigned af[2][4], bf[4][2];
            #pragma unroll
            for (int mt = 0; mt < 2; mt++) {
                const int mb = wm * 32 + mt * 16 + gid;
                af[mt][0] = f2tf32(As[st][mb][ks + tig]);
                af[mt][1] = f2tf32(As[st][mb + 8][ks + tig]);
                af[mt][2] = f2tf32(As[st][mb][ks + tig + 4]);
                af[mt][3] = f2tf32(As[st][mb + 8][ks + tig + 4]);
            }
            #pragma unroll
            for (int nt = 0; nt < 4; nt++) {
                const int nb = wn * 32 + nt * 8 + gid;
                bf[nt][0] = f2tf32(Bs[st][ks + tig][nb]);
                bf[nt][1] = f2tf32(Bs[st][ks + tig + 4][nb]);
            }
            #pragma unroll
            for (int mt = 0; mt < 2; mt++)
                #pragma unroll
                for (int nt = 0; nt < 4; nt++)
                    mma_tf32(c[mt][nt], af[mt], bf[nt]);
        }
        const int ktn = kt + 2;
        if (ktn < KT) {
            const int sn = ktn % 3;
            cp16(dA0[sn], Ag0 + ktn * 16);
            cp16(dA1[sn], Ag1 + ktn * 16);
            cp16(dB[sn],  Bg + (size_t)(ktn * 16) * ldb);
        }
        cp_commit();
    }

    #pragma unroll
    for (int mt = 0; mt < 2; mt++) {
        #pragma unroll
        for (int nt = 0; nt < 4; nt++) {
            const int r = row0 + wm * 32 + mt * 16 + gid;
            const int cc = col0 + wn * 32 + nt * 8 + 2 * tig;
            float b0 = 0.f, b1 = 0.f;
            if (MODE == 0 && bias) { b0 = bias[cc]; b1 = bias[cc + 1]; }
            C[(size_t)r * ldc + cc]           = c[mt][nt][0] + b0;
            C[(size_t)r * ldc + cc + 1]       = c[mt][nt][1] + b1;
            C[(size_t)(r + 8) * ldc + cc]     = c[mt][nt][2] + b0;
            C[(size_t)(r + 8) * ldc + cc + 1] = c[mt][nt][3] + b1;
        }
    }
}

// ---------------------------------------------------------------------------
// Scores (TF32 MMA + cp.async): G = scale*Q·K^T + sp + ed, per (b,g).
// ---------------------------------------------------------------------------
__global__ void __launch_bounds__(256)
scores_tf32_kernel(const float* __restrict__ sp, const float* __restrict__ ed) {
    const int z = blockIdx.z;
    const int b = z >> 3, g = z & 7;
    const int row0 = blockIdx.y * 128;   // s
    const int col0 = blockIdx.x * 64;    // t

    __shared__ float As[3][128][20];     // Q [s][d]
    __shared__ float Bs[3][64][20];      // K [t][d]

    const int tid = threadIdx.x;
    const int warp = tid >> 5, lane = tid & 31;
    const int gid = lane >> 2, tig = lane & 3;
    const int wm = warp & 3, wn = warp >> 2;

    float c[2][4][4] = {};

    const int a_r = tid >> 2;
    const int a_c4 = (tid & 3) * 4;
    const int bn = tid >> 2;
    const int bk4 = (tid & 3) * 4;

    const float* Qb = d_Q + ((size_t)(b * SS)) * HH + g * 64;
    const float* Kb = d_K + ((size_t)(b * SS)) * HH + g * 64;
    const float* Ag0 = Qb + (size_t)(row0 + a_r) * HH + a_c4;
    const float* Ag1 = Qb + (size_t)(row0 + a_r + 64) * HH + a_c4;
    const float* Bg  = Kb + (size_t)(col0 + bn) * HH + bk4;

    unsigned dA0[3], dA1[3], dB[3];
    #pragma unroll
    for (int s = 0; s < 3; s++) {
        dA0[s] = (unsigned)__cvta_generic_to_shared(&As[s][a_r][a_c4]);
        dA1[s] = (unsigned)__cvta_generic_to_shared(&As[s][a_r + 64][a_c4]);
        dB[s]  = (unsigned)__cvta_generic_to_shared(&Bs[s][bn][bk4]);
    }

    #pragma unroll
    for (int pf = 0; pf < 2; pf++) {
        cp16(dA0[pf], Ag0 + pf * 16);
        cp16(dA1[pf], Ag1 + pf * 16);
        cp16(dB[pf],  Bg + pf * 16);
        cp_commit();
    }

    #pragma unroll
    for (int kt = 0; kt < 4; kt++) {
        cp_wait<1>();
        __syncthreads();
        const int st = kt % 3;
        #pragma unroll
        for (int ks = 0; ks < 16; ks += 8) {
            unsigned af[2][4], bf[4][2];
            #pragma unroll
            for (int mt = 0; mt < 2; mt++) {
                const int mb = wm * 32 + mt * 16 + gid;
                af[mt][0] = f2tf32(As[st][mb][ks + tig]);
                af[mt][1] = f2tf32(As[st][mb + 8][ks + tig]);
                af[mt][2] = f2tf32(As[st][mb][ks + tig + 4]);
                af[mt][3] = f2tf32(As[st][mb + 8][ks + tig + 4]);
            }
            #pragma unroll
            for (int nt = 0; nt < 4; nt++) {
                const int nb = wn * 32 + nt * 8 + gid;
                bf[nt][0] = f2tf32(Bs[st][nb][ks + tig]);
                bf[nt][1] = f2tf32(Bs[st][nb][ks + tig + 4]);
            }
            #pragma unroll
            for (int mt = 0; mt < 2; mt++)
                #pragma unroll
                for (int nt = 0; nt < 4; nt++)
                    mma_tf32(c[mt][nt], af[mt], bf[nt]);
        }
        const int ktn = kt + 2;
        if (ktn < 4) {
            const int sn = ktn % 3;
            cp16(dA0[sn], Ag0 + ktn * 16);
            cp16(dA1[sn], Ag1 + ktn * 16);
            cp16(dB[sn],  Bg + ktn * 16);
        }
        cp_commit();
    }

    const float scale = 0.04419417382415922f;  // 512^-0.5
    float* Gb = d_G + ((size_t)z) * SS * SS;
    const float* spb = sp + ((size_t)b) * SS * SS;
    const float* edb = ed + ((size_t)b) * SS * SS;
    #pragma unroll
    for (int mt = 0; mt < 2; mt++) {
        #pragma unroll
        for (int nt = 0; nt < 4; nt++) {
            const int s = row0 + wm * 32 + mt * 16 + gid;
            const int t = col0 + wn * 32 + nt * 8 + 2 * tig;
            size_t i0 = (size_t)s * SS + t;
            size_t i1 = (size_t)(s + 8) * SS + t;
            Gb[i0]     = c[mt][nt][0] * scale + spb[i0] + edb[i0];
            Gb[i0 + 1] = c[mt][nt][1] * scale + spb[i0 + 1] + edb[i0 + 1];
            Gb[i1]     = c[mt][nt][2] * scale + spb[i1] + edb[i1];
            Gb[i1 + 1] = c[mt][nt][3] * scale + spb[i1 + 1] + edb[i1 + 1];
        }
    }
}

// ---------------------------------------------------------------------------
// Fused relu-sum-over-g + diag correction + pad + softmax.
// 512 threads per block, one block per (b,s), warp w = l-head w.
// Diagonal handled by one lane post-hoc (outside the hot loop).
// ---------------------------------------------------------------------------
__global__ void __launch_bounds__(512)
attn_softmax_kernel(const float* __restrict__ p,
                    const float* __restrict__ sigma,
                    const float* __restrict__ eps_diag) {
    const int b = blockIdx.x >> 8;
    const int s = blockIdx.x & 255;
    const int tid = threadIdx.x;
    const int warp = tid >> 5, lane = tid & 31;   // warp == l

    __shared__ float gs[GG][SS];       // 8 KB
    __shared__ float s_p[GG * LL];
    __shared__ float s_sig2[GG];
    __shared__ float s_eps[LL];
    __shared__ int s_nz[GG];

    #pragma unroll
    for (int i = tid; i < GG * SS; i += 512) {
        int g = i >> 8, t = i & 255;
        gs[g][t] = d_G[(((size_t)(b * GG + g)) * SS + s) * SS + t];
    }
    if (tid < GG * LL) s_p[tid] = p[tid];
    if (tid >= 128 && tid < 128 + GG) { float sg = sigma[tid - 128]; s_sig2[tid - 128] = sg * sg; }
    if (tid >= 160 && tid < 160 + LL) s_eps[tid - 160] = eps_diag[(tid - 160) * SS + s];
    __syncthreads();

    // pad check: warps 0..7 scan g = warp
    if (warp < GG) {
        bool nzl = false;
        #pragma unroll
        for (int tt = 0; tt < 8; tt++) nzl |= (gs[warp][lane + tt * 32] != 0.0f);
        unsigned bal = __ballot_sync(0xffffffffu, nzl);
        if (lane == 0) s_nz[warp] = (bal != 0u);
    }
    __syncthreads();
    bool zero_row = false;
    #pragma unroll
    for (int g = 0; g < GG; g++) zero_row |= (s_nz[g] == 0);

    const int l = warp;
    float pl[GG];
    #pragma unroll
    for (int g = 0; g < GG; g++) pl[g] = s_p[g * LL + l];

    // main accumulation, diagonal excluded
    float vals[8];
    #pragma unroll
    for (int tt = 0; tt < 8; tt++) {
        const int t = lane + tt * 32;
        float v = 0.f;
        #pragma unroll
        for (int g = 0; g < GG; g++)
            v += fmaxf(pl[g] * gs[g][t], 0.f);
        vals[tt] = v;
    }
    // the single lane owning t == s redoes its value with the diagonal term
    if (lane == (s & 31)) {
        const float el = s_eps[l];
        float v = 0.f;
        #pragma unroll
        for (int g = 0; g < GG; g++)
            v += fmaxf(pl[g] * (gs[g][s] + s_sig2[g] * el), 0.f);
        vals[s >> 5] = v;
    }

    // warp max
    float m = vals[0];
    #pragma unroll
    for (int tt = 1; tt < 8; tt++) m = fmaxf(m, vals[tt]);
    #pragma unroll
    for (int off = 16; off > 0; off >>= 1) m = fmaxf(m, __shfl_xor_sync(0xffffffffu, m, off));
    // exp in place + warp sum
    float sum = 0.f;
    #pragma unroll
    for (int tt = 0; tt < 8; tt++) { vals[tt] = __expf(vals[tt] - m); sum += vals[tt]; }
    #pragma unroll
    for (int off = 16; off > 0; off >>= 1) sum += __shfl_xor_sync(0xffffffffu, sum, off);
    const float inv = zero_row ? 0.f : (1.0f / sum);

    float* Arow = d_A + (((size_t)(b * LL + l)) * SS + s) * SS;
    #pragma unroll
    for (int tt = 0; tt < 8; tt++) Arow[lane + tt * 32] = vals[tt] * inv;
}

// ---------------------------------------------------------------------------
extern "C" void kernel_launch(void* const* d_in, const int* in_sizes, int n_in,
                              void* d_out, int out_size) {
    (void)in_sizes; (void)n_in; (void)out_size;
    const float* x    = (const float*)d_in[0];
    const float* sp   = (const float*)d_in[1];
    const float* ed   = (const float*)d_in[2];
    const float* Wq   = (const float*)d_in[3];
    const float* Wk   = (const float*)d_in[4];
    const float* Wv   = (const float*)d_in[5];
    const float* bv   = (const float*)d_in[6];
    const float* sig  = (const float*)d_in[7];
    const float* p    = (const float*)d_in[8];
    const float* eps  = (const float*)d_in[9];
    const float* Wout = (const float*)d_in[10];
    const float* bout = (const float*)d_in[11];
    float* out = (float*)d_out;

    float *Qp, *Kp, *Vp, *Ap, *Op;
    cudaGetSymbolAddress((void**)&Qp, d_Q);
    cudaGetSymbolAddress((void**)&Kp, d_K);
    cudaGetSymbolAddress((void**)&Vp, d_V);
    cudaGetSymbolAddress((void**)&Ap, d_A);
    cudaGetSymbolAddress((void**)&Op, d_O);

    dim3 blk(256);
    const int M = BB * SS;  // 2048
    // 1) Q+K fused projection (dual-output), V projection
    gemm_tf32_kernel<2><<<dim3(2 * HH / 64, M / 128), blk>>>(
        x, HH, Wq, HH, nullptr, Qp, HH, HH, Wk, Kp);
    gemm_tf32_kernel<0><<<dim3(LHD / 64, M / 128), blk>>>(
        x, HH, Wv, LHD, bv, Vp, LHD, HH, nullptr, nullptr);
    // 2) scores + bias
    scores_tf32_kernel<<<dim3(SS / 64, SS / 128, BB * GG), blk>>>(sp, ed);
    // 3) relu-sum over g + softmax (warp-per-l, 512 threads)
    attn_softmax_kernel<<<dim3(BB * SS), dim3(512)>>>(p, sig, eps);
    // 4) A @ V (batched over (b,l))
    gemm_tf32_kernel<1><<<dim3(1, SS / 128, BB * LL), blk>>>(
        Ap, SS, Vp, LHD, nullptr, Op, LHD, SS, nullptr, nullptr);
    // 5) output projection
    gemm_tf32_kernel<0><<<dim3(HH / 64, M / 128), blk>>>(
        Op, LHD, Wout, HH, bout, out, HH, LHD, nullptr, nullptr);
}

// round 7
// speedup vs baseline: 3.6745x; 1.0035x over previous
#include <cuda_runtime.h>
#include <cuda_bf16.h>
#include <cstdint>

// Shapes (fixed by the problem)
#define BB 8
#define SS 256
#define HH 512
#define GG 8
#define LL 16
#define HD 64
#define LHD (LL*HD)   // 1024

// Scratch (device globals — no allocation allowed)
__device__ float d_Q[BB*SS*HH];
__device__ float d_K[BB*SS*HH];
__device__ float d_V[BB*SS*LHD];
__device__ float d_G[BB*GG*SS*SS];
__device__ float d_A[BB*LL*SS*SS];
__device__ float d_O[BB*SS*LHD];

__device__ __forceinline__ unsigned f2tf32(float x) {
    unsigned r;
    asm("cvt.rna.tf32.f32 %0, %1;" : "=r"(r) : "f"(x));
    return r;
}

__device__ __forceinline__ void mma_tf32(float* c, const unsigned* a, const unsigned* b) {
    asm volatile(
        "mma.sync.aligned.m16n8k8.row.col.f32.tf32.tf32.f32 "
        "{%0,%1,%2,%3}, {%4,%5,%6,%7}, {%8,%9}, {%0,%1,%2,%3};"
        : "+f"(c[0]), "+f"(c[1]), "+f"(c[2]), "+f"(c[3])
        : "r"(a[0]), "r"(a[1]), "r"(a[2]), "r"(a[3]), "r"(b[0]), "r"(b[1]));
}

__device__ __forceinline__ void cp16(unsigned dst, const void* src) {
    asm volatile("cp.async.ca.shared.global [%0], [%1], 16;" :: "r"(dst), "l"(src));
}
__device__ __forceinline__ void cp_commit() {
    asm volatile("cp.async.commit_group;");
}
template <int N>
__device__ __forceinline__ void cp_wait() {
    asm volatile("cp.async.wait_group %0;" :: "n"(N));
}

// ---------------------------------------------------------------------------
// TF32 GEMM with cp.async 3-stage pipeline. C[M,N] = A[M,K] @ B[K,N] (+bias)
// Block tile 128x64, K-tile 16, 256 threads (8 warps: 4x2 of 32x32 warp tiles).
// MODE 0: plain. MODE 1: av-batched (z->(b,l)). MODE 2: dual-output (Q|K).
// ---------------------------------------------------------------------------
template <int MODE>
__global__ void __launch_bounds__(256)
gemm_tf32_kernel(const float* __restrict__ A, int lda,
                 const float* __restrict__ B, int ldb,
                 const float* __restrict__ bias,
                 float* __restrict__ C, int ldc,
                 int K,
                 const float* __restrict__ B2,
                 float* __restrict__ C2) {
    int col0 = blockIdx.x * 64;
    if (MODE == 1) {
        const int z = blockIdx.z;
        const int b = z >> 4, l = z & 15;
        A += (size_t)z * SS * SS;
        const size_t off = (size_t)b * SS * LHD + (size_t)l * HD;
        B += off; C += off;
    }
    if (MODE == 2) {
        if (col0 >= HH) { B = B2; C = C2; col0 -= HH; }
    }
    const int row0 = blockIdx.y * 128;

    __shared__ float As[3][128][20];   // [m][k]
    __shared__ float Bs[3][16][72];    // [k][n]

    const int tid = threadIdx.x;
    const int warp = tid >> 5, lane = tid & 31;
    const int gid = lane >> 2, tig = lane & 3;
    const int wm = warp & 3, wn = warp >> 2;

    float c[2][4][4] = {};

    const int a_r = tid >> 2;
    const int a_c4 = (tid & 3) * 4;
    const int b_k = tid >> 4;
    const int b_n4 = (tid & 15) * 4;

    const float* Ag0 = A + (size_t)(row0 + a_r) * lda + a_c4;
    const float* Ag1 = A + (size_t)(row0 + a_r + 64) * lda + a_c4;
    const float* Bg  = B + (size_t)b_k * ldb + col0 + b_n4;

    unsigned dA0[3], dA1[3], dB[3];
    #pragma unroll
    for (int s = 0; s < 3; s++) {
        dA0[s] = (unsigned)__cvta_generic_to_shared(&As[s][a_r][a_c4]);
        dA1[s] = (unsigned)__cvta_generic_to_shared(&As[s][a_r + 64][a_c4]);
        dB[s]  = (unsigned)__cvta_generic_to_shared(&Bs[s][b_k][b_n4]);
    }

    const int KT = K / 16;
    #pragma unroll
    for (int pf = 0; pf < 2; pf++) {
        cp16(dA0[pf], Ag0 + pf * 16);
        cp16(dA1[pf], Ag1 + pf * 16);
        cp16(dB[pf],  Bg + (size_t)(pf * 16) * ldb);
        cp_commit();
    }

    for (int kt = 0; kt < KT; kt++) {
        cp_wait<1>();
        __syncthreads();
        const int st = kt % 3;
        #pragma unroll
        for (int ks = 0; ks < 16; ks += 8) {
            unsigned af[2][4], bf[4][2];
            #pragma unroll
            for (int mt = 0; mt < 2; mt++) {
                const int mb = wm * 32 + mt * 16 + gid;
                af[mt][0] = f2tf32(As[st][mb][ks + tig]);
                af[mt][1] = f2tf32(As[st][mb + 8][ks + tig]);
                af[mt][2] = f2tf32(As[st][mb][ks + tig + 4]);
                af[mt][3] = f2tf32(As[st][mb + 8][ks + tig + 4]);
            }
            #pragma unroll
            for (int nt = 0; nt < 4; nt++) {
                const int nb = wn * 32 + nt * 8 + gid;
                bf[nt][0] = f2tf32(Bs[st][ks + tig][nb]);
                bf[nt][1] = f2tf32(Bs[st][ks + tig + 4][nb]);
            }
            #pragma unroll
            for (int mt = 0; mt < 2; mt++)
                #pragma unroll
                for (int nt = 0; nt < 4; nt++)
                    mma_tf32(c[mt][nt], af[mt], bf[nt]);
        }
        const int ktn = kt + 2;
        if (ktn < KT) {
            const int sn = ktn % 3;
            cp16(dA0[sn], Ag0 + ktn * 16);
            cp16(dA1[sn], Ag1 + ktn * 16);
            cp16(dB[sn],  Bg + (size_t)(ktn * 16) * ldb);
        }
        cp_commit();
    }

    #pragma unroll
    for (int mt = 0; mt < 2; mt++) {
        #pragma unroll
        for (int nt = 0; nt < 4; nt++) {
            const int r = row0 + wm * 32 + mt * 16 + gid;
            const int cc = col0 + wn * 32 + nt * 8 + 2 * tig;
            float b0 = 0.f, b1 = 0.f;
            if (MODE == 0 && bias) { b0 = bias[cc]; b1 = bias[cc + 1]; }
            C[(size_t)r * ldc + cc]           = c[mt][nt][0] + b0;
            C[(size_t)r * ldc + cc + 1]       = c[mt][nt][1] + b1;
            C[(size_t)(r + 8) * ldc + cc]     = c[mt][nt][2] + b0;
            C[(size_t)(r + 8) * ldc + cc + 1] = c[mt][nt][3] + b1;
        }
    }
}

// ---------------------------------------------------------------------------
// Scores (TF32 MMA + cp.async): G = scale*Q·K^T + sp + ed, per (b,g).
// ---------------------------------------------------------------------------
__global__ void __launch_bounds__(256)
scores_tf32_kernel(const float* __restrict__ sp, const float* __restrict__ ed) {
    const int z = blockIdx.z;
    const int b = z >> 3, g = z & 7;
    const int row0 = blockIdx.y * 128;   // s
    const int col0 = blockIdx.x * 64;    // t

    __shared__ float As[3][128][20];     // Q [s][d]
    __shared__ float Bs[3][64][20];      // K [t][d]

    const int tid = threadIdx.x;
    const int warp = tid >> 5, lane = tid & 31;
    const int gid = lane >> 2, tig = lane & 3;
    const int wm = warp & 3, wn = warp >> 2;

    float c[2][4][4] = {};

    const int a_r = tid >> 2;
    const int a_c4 = (tid & 3) * 4;
    const int bn = tid >> 2;
    const int bk4 = (tid & 3) * 4;

    const float* Qb = d_Q + ((size_t)(b * SS)) * HH + g * 64;
    const float* Kb = d_K + ((size_t)(b * SS)) * HH + g * 64;
    const float* Ag0 = Qb + (size_t)(row0 + a_r) * HH + a_c4;
    const float* Ag1 = Qb + (size_t)(row0 + a_r + 64) * HH + a_c4;
    const float* Bg  = Kb + (size_t)(col0 + bn) * HH + bk4;

    unsigned dA0[3], dA1[3], dB[3];
    #pragma unroll
    for (int s = 0; s < 3; s++) {
        dA0[s] = (unsigned)__cvta_generic_to_shared(&As[s][a_r][a_c4]);
        dA1[s] = (unsigned)__cvta_generic_to_shared(&As[s][a_r + 64][a_c4]);
        dB[s]  = (unsigned)__cvta_generic_to_shared(&Bs[s][bn][bk4]);
    }

    #pragma unroll
    for (int pf = 0; pf < 2; pf++) {
        cp16(dA0[pf], Ag0 + pf * 16);
        cp16(dA1[pf], Ag1 + pf * 16);
        cp16(dB[pf],  Bg + pf * 16);
        cp_commit();
    }

    #pragma unroll
    for (int kt = 0; kt < 4; kt++) {
        cp_wait<1>();
        __syncthreads();
        const int st = kt % 3;
        #pragma unroll
        for (int ks = 0; ks < 16; ks += 8) {
            unsigned af[2][4], bf[4][2];
            #pragma unroll
            for (int mt = 0; mt < 2; mt++) {
                const int mb = wm * 32 + mt * 16 + gid;
                af[mt][0] = f2tf32(As[st][mb][ks + tig]);
                af[mt][1] = f2tf32(As[st][mb + 8][ks + tig]);
                af[mt][2] = f2tf32(As[st][mb][ks + tig + 4]);
                af[mt][3] = f2tf32(As[st][mb + 8][ks + tig + 4]);
            }
            #pragma unroll
            for (int nt = 0; nt < 4; nt++) {
                const int nb = wn * 32 + nt * 8 + gid;
                bf[nt][0] = f2tf32(Bs[st][nb][ks + tig]);
                bf[nt][1] = f2tf32(Bs[st][nb][ks + tig + 4]);
            }
            #pragma unroll
            for (int mt = 0; mt < 2; mt++)
                #pragma unroll
                for (int nt = 0; nt < 4; nt++)
                    mma_tf32(c[mt][nt], af[mt], bf[nt]);
        }
        const int ktn = kt + 2;
        if (ktn < 4) {
            const int sn = ktn % 3;
            cp16(dA0[sn], Ag0 + ktn * 16);
            cp16(dA1[sn], Ag1 + ktn * 16);
            cp16(dB[sn],  Bg + ktn * 16);
        }
        cp_commit();
    }

    const float scale = 0.04419417382415922f;  // 512^-0.5
    float* Gb = d_G + ((size_t)z) * SS * SS;
    const float* spb = sp + ((size_t)b) * SS * SS;
    const float* edb = ed + ((size_t)b) * SS * SS;
    #pragma unroll
    for (int mt = 0; mt < 2; mt++) {
        #pragma unroll
        for (int nt = 0; nt < 4; nt++) {
            const int s = row0 + wm * 32 + mt * 16 + gid;
            const int t = col0 + wn * 32 + nt * 8 + 2 * tig;
            size_t i0 = (size_t)s * SS + t;
            size_t i1 = (size_t)(s + 8) * SS + t;
            Gb[i0]     = c[mt][nt][0] * scale + spb[i0] + edb[i0];
            Gb[i0 + 1] = c[mt][nt][1] * scale + spb[i0 + 1] + edb[i0 + 1];
            Gb[i1]     = c[mt][nt][2] * scale + spb[i1] + edb[i1];
            Gb[i1 + 1] = c[mt][nt][3] * scale + spb[i1 + 1] + edb[i1 + 1];
        }
    }
}

// ---------------------------------------------------------------------------
// Fused relu-sum-over-g + diag correction + pad + softmax.
// 512 threads per block, one block per (b,s), warp w = l-head w.
// Diagonal handled by one lane post-hoc (outside the hot loop).
// ---------------------------------------------------------------------------
__global__ void __launch_bounds__(512)
attn_softmax_kernel(const float* __restrict__ p,
                    const float* __restrict__ sigma,
                    const float* __restrict__ eps_diag) {
    const int b = blockIdx.x >> 8;
    const int s = blockIdx.x & 255;
    const int tid = threadIdx.x;
    const int warp = tid >> 5, lane = tid & 31;   // warp == l

    __shared__ float gs[GG][SS];       // 8 KB
    __shared__ float s_p[GG * LL];
    __shared__ float s_sig2[GG];
    __shared__ float s_eps[LL];
    __shared__ int s_nz[GG];

    #pragma unroll
    for (int i = tid; i < GG * SS; i += 512) {
        int g = i >> 8, t = i & 255;
        gs[g][t] = d_G[(((size_t)(b * GG + g)) * SS + s) * SS + t];
    }
    if (tid < GG * LL) s_p[tid] = p[tid];
    if (tid >= 128 && tid < 128 + GG) { float sg = sigma[tid - 128]; s_sig2[tid - 128] = sg * sg; }
    if (tid >= 160 && tid < 160 + LL) s_eps[tid - 160] = eps_diag[(tid - 160) * SS + s];
    __syncthreads();

    // pad check: warps 0..7 scan g = warp
    if (warp < GG) {
        bool nzl = false;
        #pragma unroll
        for (int tt = 0; tt < 8; tt++) nzl |= (gs[warp][lane + tt * 32] != 0.0f);
        unsigned bal = __ballot_sync(0xffffffffu, nzl);
        if (lane == 0) s_nz[warp] = (bal != 0u);
    }
    __syncthreads();
    bool zero_row = false;
    #pragma unroll
    for (int g = 0; g < GG; g++) zero_row |= (s_nz[g] == 0);

    const int l = warp;
    float pl[GG];
    #pragma unroll
    for (int g = 0; g < GG; g++) pl[g] = s_p[g * LL + l];

    // main accumulation, diagonal excluded
    float vals[8];
    #pragma unroll
    for (int tt = 0; tt < 8; tt++) {
        const int t = lane + tt * 32;
        float v = 0.f;
        #pragma unroll
        for (int g = 0; g < GG; g++)
            v += fmaxf(pl[g] * gs[g][t], 0.f);
        vals[tt] = v;
    }
    // the single lane owning t == s redoes its value with the diagonal term
    if (lane == (s & 31)) {
        const float el = s_eps[l];
        float v = 0.f;
        #pragma unroll
        for (int g = 0; g < GG; g++)
            v += fmaxf(pl[g] * (gs[g][s] + s_sig2[g] * el), 0.f);
        vals[s >> 5] = v;
    }

    // warp max
    float m = vals[0];
    #pragma unroll
    for (int tt = 1; tt < 8; tt++) m = fmaxf(m, vals[tt]);
    #pragma unroll
    for (int off = 16; off > 0; off >>= 1) m = fmaxf(m, __shfl_xor_sync(0xffffffffu, m, off));
    // exp in place + warp sum
    float sum = 0.f;
    #pragma unroll
    for (int tt = 0; tt < 8; tt++) { vals[tt] = __expf(vals[tt] - m); sum += vals[tt]; }
    #pragma unroll
    for (int off = 16; off > 0; off >>= 1) sum += __shfl_xor_sync(0xffffffffu, sum, off);
    const float inv = zero_row ? 0.f : (1.0f / sum);

    float* Arow = d_A + (((size_t)(b * LL + l)) * SS + s) * SS;
    #pragma unroll
    for (int tt = 0; tt < 8; tt++) Arow[lane + tt * 32] = vals[tt] * inv;
}

// ---------------------------------------------------------------------------
extern "C" void kernel_launch(void* const* d_in, const int* in_sizes, int n_in,
                              void* d_out, int out_size) {
    (void)in_sizes; (void)n_in; (void)out_size;
    const float* x    = (const float*)d_in[0];
    const float* sp   = (const float*)d_in[1];
    const float* ed   = (const float*)d_in[2];
    const float* Wq   = (const float*)d_in[3];
    const float* Wk   = (const float*)d_in[4];
    const float* Wv   = (const float*)d_in[5];
    const float* bv   = (const float*)d_in[6];
    const float* sig  = (const float*)d_in[7];
    const float* p    = (const float*)d_in[8];
    const float* eps  = (const float*)d_in[9];
    const float* Wout = (const float*)d_in[10];
    const float* bout = (const float*)d_in[11];
    float* out = (float*)d_out;

    float *Qp, *Kp, *Vp, *Ap, *Op;
    cudaGetSymbolAddress((void**)&Qp, d_Q);
    cudaGetSymbolAddress((void**)&Kp, d_K);
    cudaGetSymbolAddress((void**)&Vp, d_V);
    cudaGetSymbolAddress((void**)&Ap, d_A);
    cudaGetSymbolAddress((void**)&Op, d_O);

    dim3 blk(256);
    const int M = BB * SS;  // 2048
    // 1) Q+K fused projection (dual-output), V projection
    gemm_tf32_kernel<2><<<dim3(2 * HH / 64, M / 128), blk>>>(
        x, HH, Wq, HH, nullptr, Qp, HH, HH, Wk, Kp);
    gemm_tf32_kernel<0><<<dim3(LHD / 64, M / 128), blk>>>(
        x, HH, Wv, LHD, bv, Vp, LHD, HH, nullptr, nullptr);
    // 2) scores + bias
    scores_tf32_kernel<<<dim3(SS / 64, SS / 128, BB * GG), blk>>>(sp, ed);
    // 3) relu-sum over g + softmax (warp-per-l, 512 threads)
    attn_softmax_kernel<<<dim3(BB * SS), dim3(512)>>>(p, sig, eps);
    // 4) A @ V (batched over (b,l))
    gemm_tf32_kernel<1><<<dim3(1, SS / 128, BB * LL), blk>>>(
        Ap, SS, Vp, LHD, nullptr, Op, LHD, SS, nullptr, nullptr);
    // 5) output projection
    gemm_tf32_kernel<0><<<dim3(HH / 64, M / 128), blk>>>(
        Op, LHD, Wout, HH, bout, out, HH, LHD, nullptr, nullptr);
}